// round 2
// baseline (speedup 1.0000x reference)
#include <cuda_runtime.h>
#include <cuda_bf16.h>
#include <cstdint>

#define B_SZ 4096
#define D_SZ 1024
#define C_SZ 32
#define TEMP_INV 10.0f

#define BM 128
#define BN 128
#define BK 32
#define SK 40           // padded halves per smem row (32 data + 8 pad) -> conflict-free ldmatrix
#define TTOT (B_SZ/BM)  // 32 tiles per dim
#define NPAIR (TTOT*(TTOT+1)/2)  // 528 triangular blocks

// ---------------- device scratch (no allocations allowed) ----------------
__device__ __align__(128) __nv_bfloat16 g_rn[B_SZ * D_SZ];   // normalized rows, bf16
__device__ float g_rowsumE[B_SZ];
__device__ float g_u[D_SZ * C_SZ];   // u[d][c] = (RN^T @ soft)[d][c]
__device__ float g_m[D_SZ * C_SZ];   // m[d][g] = group sums of rn
__device__ float g_Ssum[C_SZ];
__device__ int   g_hist[C_SZ];
__device__ int   g_labels[B_SZ];
__device__ float g_diagsum;
__device__ float g_accLog;
__device__ float g_sumU2;
__device__ float g_sumM2;

// ---------------- helpers ----------------
__device__ __forceinline__ float decode_pw(const void* p) {
    // pseudo_weight may arrive as int32/int64 (LE low word) or float32
    int v0 = ((const int*)p)[0];
    if (v0 > 0 && v0 < (1 << 26)) return (float)v0;
    float f = __int_as_float(v0);
    if (f > 0.0f && f < 1e8f) return f;
    return 0.0f;
}

__device__ __forceinline__ unsigned smem_u32(const void* p) {
    return (unsigned)__cvta_generic_to_shared(p);
}
__device__ __forceinline__ void ldm_x4(unsigned addr, unsigned &r0, unsigned &r1, unsigned &r2, unsigned &r3) {
    asm volatile("ldmatrix.sync.aligned.m8n8.x4.shared.b16 {%0,%1,%2,%3}, [%4];"
                 : "=r"(r0), "=r"(r1), "=r"(r2), "=r"(r3) : "r"(addr));
}
__device__ __forceinline__ void ldm_x2(unsigned addr, unsigned &r0, unsigned &r1) {
    asm volatile("ldmatrix.sync.aligned.m8n8.x2.shared.b16 {%0,%1}, [%2];"
                 : "=r"(r0), "=r"(r1) : "r"(addr));
}
__device__ __forceinline__ void mma16816(float &c0, float &c1, float &c2, float &c3,
                                         unsigned a0, unsigned a1, unsigned a2, unsigned a3,
                                         unsigned b0, unsigned b1) {
    asm volatile("mma.sync.aligned.m16n8k16.row.col.f32.bf16.bf16.f32 "
                 "{%0,%1,%2,%3},{%4,%5,%6,%7},{%8,%9},{%0,%1,%2,%3};"
                 : "+f"(c0), "+f"(c1), "+f"(c2), "+f"(c3)
                 : "r"(a0), "r"(a1), "r"(a2), "r"(a3), "r"(b0), "r"(b1));
}

// ---------------- kernels ----------------
__global__ void k_zero() {
    int i = blockIdx.x * 256 + threadIdx.x;
    if (i < B_SZ) g_rowsumE[i] = 0.f;
    if (i < D_SZ * C_SZ) { g_u[i] = 0.f; g_m[i] = 0.f; }
    if (i < C_SZ) { g_Ssum[i] = 0.f; g_hist[i] = 0; }
    if (i == 0) { g_diagsum = 0.f; g_accLog = 0.f; g_sumU2 = 0.f; g_sumM2 = 0.f; }
}

__global__ void k_labels(const int* __restrict__ p) {
    __shared__ int is64;
    if (threadIdx.x == 0) {
        int any = 0;
        #pragma unroll
        for (int i = 1; i < 128; i += 2) any |= p[i];
        is64 = (any == 0) ? 1 : 0;   // int64 labels: odd LE words are all 0
    }
    __syncthreads();
    int s64 = is64;
    for (int i = blockIdx.x * blockDim.x + threadIdx.x; i < B_SZ; i += gridDim.x * blockDim.x)
        g_labels[i] = s64 ? p[2 * i] : p[i];
}

// normalize rows -> bf16, group sums (g_m via atomics), diagsum, Ssum, hist
__global__ void k_norm(const float* __restrict__ reps, const float* __restrict__ soft) {
    int row = blockIdx.x;
    const float* x = reps + (size_t)row * D_SZ;
    float ss = 0.f;
    for (int k = threadIdx.x; k < D_SZ; k += 256) { float v = x[k]; ss += v * v; }
    __shared__ float red[8];
    #pragma unroll
    for (int o = 16; o; o >>= 1) ss += __shfl_xor_sync(~0u, ss, o);
    if ((threadIdx.x & 31) == 0) red[threadIdx.x >> 5] = ss;
    __syncthreads();
    if (threadIdx.x < 8) {
        float v = red[threadIdx.x];
        #pragma unroll
        for (int o = 4; o; o >>= 1) v += __shfl_xor_sync(0xff, v, o);
        if (threadIdx.x == 0) red[0] = v;
    }
    __syncthreads();
    float sumsq = red[0];
    float inv = 1.0f / fmaxf(sqrtf(sumsq), 1e-8f);
    int lbl = g_labels[row];
    for (int k = threadIdx.x; k < D_SZ; k += 256) {
        float v = x[k] * inv;
        g_rn[(size_t)row * D_SZ + k] = __float2bfloat16(v);
        atomicAdd(&g_m[k * C_SZ + lbl], v);
    }
    if (threadIdx.x == 0) {
        atomicAdd(&g_diagsum, sumsq * inv * inv);
        atomicAdd(&g_hist[lbl], 1);
    }
    if (threadIdx.x < C_SZ) atomicAdd(&g_Ssum[threadIdx.x], soft[(size_t)row * C_SZ + threadIdx.x]);
}

// u = RN^T @ soft   (split-k over row chunks of 128)
__global__ void k_um(const float* __restrict__ soft) {
    int d = blockIdx.x * 128 + threadIdx.x;
    int i0 = blockIdx.y * 128;
    float uacc[C_SZ];
    #pragma unroll
    for (int c = 0; c < C_SZ; c++) uacc[c] = 0.f;
    for (int i = i0; i < i0 + 128; i++) {
        float r = __bfloat162float(g_rn[(size_t)i * D_SZ + d]);
        const float4* s4 = (const float4*)(soft + (size_t)i * C_SZ);
        #pragma unroll
        for (int q = 0; q < 8; q++) {
            float4 sv = __ldg(s4 + q);
            uacc[q * 4 + 0] = fmaf(r, sv.x, uacc[q * 4 + 0]);
            uacc[q * 4 + 1] = fmaf(r, sv.y, uacc[q * 4 + 1]);
            uacc[q * 4 + 2] = fmaf(r, sv.z, uacc[q * 4 + 2]);
            uacc[q * 4 + 3] = fmaf(r, sv.w, uacc[q * 4 + 3]);
        }
    }
    #pragma unroll
    for (int c = 0; c < C_SZ; c++) atomicAdd(&g_u[d * C_SZ + c], uacc[c]);
}

// main pass: rowsumE[i] = sum_{j!=i} exp(Z_ij), triangular 128x128 tiles, bf16 mma
__global__ __launch_bounds__(256) void k_gemm() {
    __shared__ __align__(16) __nv_bfloat16 sA[2][BM][SK];
    __shared__ __align__(16) __nv_bfloat16 sB[2][BN][SK];
    __shared__ float rowbuf[BM];
    __shared__ float colbuf[BN];

    // map block -> triangular (I,J), I<=J
    int idx = blockIdx.x;
    int I = 0;
    while (idx >= (TTOT - I)) { idx -= (TTOT - I); ++I; }
    int J = I + idx;
    bool diag = (I == J);

    int tid = threadIdx.x;
    int wid = tid >> 5, lane = tid & 31;
    int wm = wid & 1, wn = wid >> 1;     // warps 2 x 4; warp tile 64x32

    if (tid < BM) { rowbuf[tid] = 0.f; colbuf[tid] = 0.f; }

    const __nv_bfloat16* gA = g_rn + (size_t)I * BM * D_SZ;
    const __nv_bfloat16* gB = g_rn + (size_t)J * BN * D_SZ;

    int lrow = tid >> 1, lseg = tid & 1;   // each thread loads 2x uint4 per tile

    float acc[4][4][4];
    #pragma unroll
    for (int a = 0; a < 4; a++)
        #pragma unroll
        for (int b = 0; b < 4; b++)
            #pragma unroll
            for (int c = 0; c < 4; c++) acc[a][b][c] = 0.f;

    {   // preload k-tile 0
        const uint4* pa = (const uint4*)(gA + (size_t)lrow * D_SZ) + lseg * 2;
        const uint4* pb = (const uint4*)(gB + (size_t)lrow * D_SZ) + lseg * 2;
        *(uint4*)&sA[0][lrow][lseg * 16]     = pa[0];
        *(uint4*)&sA[0][lrow][lseg * 16 + 8] = pa[1];
        *(uint4*)&sB[0][lrow][lseg * 16]     = pb[0];
        *(uint4*)&sB[0][lrow][lseg * 16 + 8] = pb[1];
    }
    __syncthreads();

    const int KT = D_SZ / BK;   // 32
    for (int kt = 0; kt < KT; ++kt) {
        uint4 ra0, ra1, rb0, rb1;
        if (kt + 1 < KT) {
            const uint4* pa = (const uint4*)(gA + (size_t)lrow * D_SZ + (kt + 1) * BK) + lseg * 2;
            const uint4* pb = (const uint4*)(gB + (size_t)lrow * D_SZ + (kt + 1) * BK) + lseg * 2;
            ra0 = pa[0]; ra1 = pa[1]; rb0 = pb[0]; rb1 = pb[1];
        }
        int buf = kt & 1;
        #pragma unroll
        for (int s = 0; s < 2; s++) {
            unsigned a[4][4], b[4][2];
            #pragma unroll
            for (int mi = 0; mi < 4; mi++) {
                unsigned addr = smem_u32(&sA[buf][wm * 64 + mi * 16 + (lane & 15)][s * 16 + (lane >> 4) * 8]);
                ldm_x4(addr, a[mi][0], a[mi][1], a[mi][2], a[mi][3]);
            }
            #pragma unroll
            for (int ni = 0; ni < 4; ni++) {
                unsigned addr = smem_u32(&sB[buf][wn * 32 + ni * 8 + (lane & 7)][s * 16 + ((lane >> 3) & 1) * 8]);
                ldm_x2(addr, b[ni][0], b[ni][1]);
            }
            #pragma unroll
            for (int mi = 0; mi < 4; mi++)
                #pragma unroll
                for (int ni = 0; ni < 4; ni++)
                    mma16816(acc[mi][ni][0], acc[mi][ni][1], acc[mi][ni][2], acc[mi][ni][3],
                             a[mi][0], a[mi][1], a[mi][2], a[mi][3], b[ni][0], b[ni][1]);
        }
        if (kt + 1 < KT) {
            int nb = buf ^ 1;
            *(uint4*)&sA[nb][lrow][lseg * 16]     = ra0;
            *(uint4*)&sA[nb][lrow][lseg * 16 + 8] = ra1;
            *(uint4*)&sB[nb][lrow][lseg * 16]     = rb0;
            *(uint4*)&sB[nb][lrow][lseg * 16 + 8] = rb1;
        }
        __syncthreads();
    }

    // epilogue: e = exp(acc*10); accumulate row sums (I) and col sums (J)
    int g = lane >> 2, t = lane & 3;
    int rbase = wm * 64, cbase = wn * 32;
    float colp[4][2];
    #pragma unroll
    for (int ni = 0; ni < 4; ni++) { colp[ni][0] = 0.f; colp[ni][1] = 0.f; }

    #pragma unroll
    for (int mi = 0; mi < 4; mi++) {
        float r0 = 0.f, r1 = 0.f;
        #pragma unroll
        for (int ni = 0; ni < 4; ni++) {
            float e0 = __expf(acc[mi][ni][0] * TEMP_INV);
            float e1 = __expf(acc[mi][ni][1] * TEMP_INV);
            float e2 = __expf(acc[mi][ni][2] * TEMP_INV);
            float e3 = __expf(acc[mi][ni][3] * TEMP_INV);
            if (diag) {
                int r = rbase + mi * 16 + g, c = cbase + ni * 8 + t * 2;
                if (r == c)     e0 = 0.f;
                if (r == c + 1) e1 = 0.f;
                if (r + 8 == c)     e2 = 0.f;
                if (r + 8 == c + 1) e3 = 0.f;
            }
            r0 += e0 + e1; r1 += e2 + e3;
            colp[ni][0] += e0 + e2; colp[ni][1] += e1 + e3;
        }
        r0 += __shfl_xor_sync(~0u, r0, 1); r0 += __shfl_xor_sync(~0u, r0, 2);
        r1 += __shfl_xor_sync(~0u, r1, 1); r1 += __shfl_xor_sync(~0u, r1, 2);
        if (t == 0) {
            atomicAdd(&rowbuf[rbase + mi * 16 + g],     r0);
            atomicAdd(&rowbuf[rbase + mi * 16 + g + 8], r1);
        }
    }
    if (!diag) {
        #pragma unroll
        for (int ni = 0; ni < 4; ni++) {
            #pragma unroll
            for (int p = 0; p < 2; p++) {
                float v = colp[ni][p];
                v += __shfl_xor_sync(~0u, v, 4);
                v += __shfl_xor_sync(~0u, v, 8);
                v += __shfl_xor_sync(~0u, v, 16);
                if (lane < 4) atomicAdd(&colbuf[cbase + ni * 8 + lane * 2 + p], v);
            }
        }
    }
    __syncthreads();
    if (tid < BM) {
        atomicAdd(&g_rowsumE[I * BM + tid], rowbuf[tid]);
        if (!diag) atomicAdd(&g_rowsumE[J * BN + tid], colbuf[tid]);
    }
}

__global__ void k_sumsq() {
    float su = 0.f, sm = 0.f;
    for (int i = blockIdx.x * blockDim.x + threadIdx.x; i < D_SZ * C_SZ; i += gridDim.x * blockDim.x) {
        float a = g_u[i]; su += a * a;
        float b = g_m[i]; sm += b * b;
    }
    #pragma unroll
    for (int o = 16; o; o >>= 1) { su += __shfl_xor_sync(~0u, su, o); sm += __shfl_xor_sync(~0u, sm, o); }
    __shared__ float rs[8], rm[8];
    if ((threadIdx.x & 31) == 0) { rs[threadIdx.x >> 5] = su; rm[threadIdx.x >> 5] = sm; }
    __syncthreads();
    if (threadIdx.x < 8) {
        float a = rs[threadIdx.x], b = rm[threadIdx.x];
        #pragma unroll
        for (int o = 4; o; o >>= 1) { a += __shfl_xor_sync(0xff, a, o); b += __shfl_xor_sync(0xff, b, o); }
        if (threadIdx.x == 0) { atomicAdd(&g_sumU2, a); atomicAdd(&g_sumM2, b); }
    }
}

__global__ void k_rowterms(const float* __restrict__ soft, const void* pwp) {
    float pw = decode_pw(pwp);
    int i = blockIdx.x * blockDim.x + threadIdx.x;
    float term = 0.f;
    if (i < B_SZ) {
        int lbl = g_labels[i];
        float wsum = (float)(g_hist[lbl] - 1);
        const float* s = soft + (size_t)i * C_SZ;
        float d = 0.f;
        #pragma unroll
        for (int c = 0; c < C_SZ; c++) d += s[c] * g_Ssum[c];
        wsum += pw * d;
        term = wsum * logf(g_rowsumE[i]);
    }
    #pragma unroll
    for (int o = 16; o; o >>= 1) term += __shfl_xor_sync(~0u, term, o);
    __shared__ float red[8];
    if ((threadIdx.x & 31) == 0) red[threadIdx.x >> 5] = term;
    __syncthreads();
    if (threadIdx.x < 8) {
        float v = red[threadIdx.x];
        #pragma unroll
        for (int o = 4; o; o >>= 1) v += __shfl_xor_sync(0xff, v, o);
        if (threadIdx.x == 0) atomicAdd(&g_accLog, v);
    }
}

__global__ void k_out(float* out, const void* pwp) {
    float pw = decode_pw(pwp);
    float P  = (g_sumM2 - g_diagsum) * TEMP_INV;   // sum over same-label pairs (i != j) of Z
    float SZ = g_sumU2 * TEMP_INV;                 // sum over all pairs of soft_sim * Z
    out[0] = (g_accLog - P - pw * SZ) / (float)B_SZ;
}

// ---------------- launch ----------------
extern "C" void kernel_launch(void* const* d_in, const int* in_sizes, int n_in,
                              void* d_out, int out_size) {
    const float* reps = (const float*)d_in[0];
    const float* soft = (const float*)d_in[1];
    const int*   lblp = (const int*)d_in[2];
    const void*  pwp  = d_in[3];
    float* out = (float*)d_out;
    (void)in_sizes; (void)n_in; (void)out_size;

    k_zero<<<128, 256>>>();
    k_labels<<<16, 256>>>(lblp);
    k_norm<<<B_SZ, 256>>>(reps, soft);
    k_um<<<dim3(D_SZ / 128, B_SZ / 128), 128>>>(soft);
    k_gemm<<<NPAIR, 256>>>();
    k_sumsq<<<32, 256>>>();
    k_rowterms<<<B_SZ / 256, 256>>>(soft, pwp);
    k_out<<<1, 1>>>(out, pwp);
}

// round 3
// speedup vs baseline: 1.6427x; 1.6427x over previous
#include <cuda_runtime.h>
#include <cuda_bf16.h>
#include <cstdint>

#define B_SZ 4096
#define D_SZ 1024
#define C_SZ 32
#define TEMP_INV 10.0f

#define BM 128
#define BN 128
#define BK 32
#define SK 40           // padded halves per smem row (32 data + 8 pad) -> conflict-free ldmatrix
#define TTOT (B_SZ/BM)  // 32 tiles per dim
#define NPAIR (TTOT*(TTOT+1)/2)  // 528 triangular blocks

// small GEMM (U | M) config: RN^T [1024 x 4096] @ [soft | onehot] [4096 x 64]
#define KSPLIT 8
#define KCH (B_SZ/KSPLIT)   // 512
#define NSM 64              // 32 soft cols + 32 one-hot cols

// ---------------- device scratch (no allocations allowed) ----------------
__device__ __align__(128) __nv_bfloat16 g_rn[B_SZ * D_SZ];   // normalized rows, bf16
__device__ float g_rowsumE[B_SZ];
__device__ float g_part[KSPLIT * 8 * 128 * NSM];   // split-k partials of [U|M], 2MB
__device__ float g_Ssum[C_SZ];
__device__ int   g_hist[C_SZ];
__device__ int   g_labels[B_SZ];
__device__ float g_diagsum;
__device__ float g_accLog;
__device__ float g_sumU2;
__device__ float g_sumM2;

// ---------------- helpers ----------------
__device__ __forceinline__ float decode_pw(const void* p) {
    int v0 = ((const int*)p)[0];
    if (v0 > 0 && v0 < (1 << 26)) return (float)v0;
    float f = __int_as_float(v0);
    if (f > 0.0f && f < 1e8f) return f;
    return 0.0f;
}

__device__ __forceinline__ unsigned smem_u32(const void* p) {
    return (unsigned)__cvta_generic_to_shared(p);
}
__device__ __forceinline__ void ldm_x4(unsigned addr, unsigned &r0, unsigned &r1, unsigned &r2, unsigned &r3) {
    asm volatile("ldmatrix.sync.aligned.m8n8.x4.shared.b16 {%0,%1,%2,%3}, [%4];"
                 : "=r"(r0), "=r"(r1), "=r"(r2), "=r"(r3) : "r"(addr));
}
__device__ __forceinline__ void ldm_x2(unsigned addr, unsigned &r0, unsigned &r1) {
    asm volatile("ldmatrix.sync.aligned.m8n8.x2.shared.b16 {%0,%1}, [%2];"
                 : "=r"(r0), "=r"(r1) : "r"(addr));
}
__device__ __forceinline__ void ldm_x4_t(unsigned addr, unsigned &r0, unsigned &r1, unsigned &r2, unsigned &r3) {
    asm volatile("ldmatrix.sync.aligned.m8n8.x4.trans.shared.b16 {%0,%1,%2,%3}, [%4];"
                 : "=r"(r0), "=r"(r1), "=r"(r2), "=r"(r3) : "r"(addr));
}
__device__ __forceinline__ void ldm_x2_t(unsigned addr, unsigned &r0, unsigned &r1) {
    asm volatile("ldmatrix.sync.aligned.m8n8.x2.trans.shared.b16 {%0,%1}, [%2];"
                 : "=r"(r0), "=r"(r1) : "r"(addr));
}
__device__ __forceinline__ void mma16816(float &c0, float &c1, float &c2, float &c3,
                                         unsigned a0, unsigned a1, unsigned a2, unsigned a3,
                                         unsigned b0, unsigned b1) {
    asm volatile("mma.sync.aligned.m16n8k16.row.col.f32.bf16.bf16.f32 "
                 "{%0,%1,%2,%3},{%4,%5,%6,%7},{%8,%9},{%0,%1,%2,%3};"
                 : "+f"(c0), "+f"(c1), "+f"(c2), "+f"(c3)
                 : "r"(a0), "r"(a1), "r"(a2), "r"(a3), "r"(b0), "r"(b1));
}

// ---------------- kernels ----------------
__global__ void k_zero() {
    int i = blockIdx.x * 256 + threadIdx.x;
    if (i < B_SZ) g_rowsumE[i] = 0.f;
    if (i < C_SZ) { g_Ssum[i] = 0.f; g_hist[i] = 0; }
    if (i == 0) { g_diagsum = 0.f; g_accLog = 0.f; g_sumU2 = 0.f; g_sumM2 = 0.f; }
}

__global__ void k_labels(const int* __restrict__ p) {
    __shared__ int is64;
    if (threadIdx.x == 0) {
        int any = 0;
        #pragma unroll
        for (int i = 1; i < 128; i += 2) any |= p[i];
        is64 = (any == 0) ? 1 : 0;   // int64 labels: odd LE words are all 0
    }
    __syncthreads();
    int s64 = is64;
    for (int i = blockIdx.x * blockDim.x + threadIdx.x; i < B_SZ; i += gridDim.x * blockDim.x)
        g_labels[i] = s64 ? p[2 * i] : p[i];
}

// normalize rows -> bf16; diagsum, Ssum, hist (group sums M now computed in k_small)
__global__ void k_norm(const float* __restrict__ reps, const float* __restrict__ soft) {
    int row = blockIdx.x;
    const float* x = reps + (size_t)row * D_SZ;
    float ss = 0.f;
    for (int k = threadIdx.x; k < D_SZ; k += 256) { float v = x[k]; ss += v * v; }
    __shared__ float red[8];
    #pragma unroll
    for (int o = 16; o; o >>= 1) ss += __shfl_xor_sync(~0u, ss, o);
    if ((threadIdx.x & 31) == 0) red[threadIdx.x >> 5] = ss;
    __syncthreads();
    if (threadIdx.x < 8) {
        float v = red[threadIdx.x];
        #pragma unroll
        for (int o = 4; o; o >>= 1) v += __shfl_xor_sync(0xff, v, o);
        if (threadIdx.x == 0) red[0] = v;
    }
    __syncthreads();
    float sumsq = red[0];
    float inv = 1.0f / fmaxf(sqrtf(sumsq), 1e-8f);
    for (int k = threadIdx.x; k < D_SZ; k += 256) {
        float v = x[k] * inv;
        g_rn[(size_t)row * D_SZ + k] = __float2bfloat16(v);
    }
    if (threadIdx.x == 0) {
        atomicAdd(&g_diagsum, sumsq * inv * inv);
        atomicAdd(&g_hist[g_labels[row]], 1);
    }
    if (threadIdx.x < C_SZ) atomicAdd(&g_Ssum[threadIdx.x], soft[(size_t)row * C_SZ + threadIdx.x]);
}

// [U | M] = RN^T @ [soft | onehot], bf16 mma with ldmatrix.trans, split-k partials
__global__ __launch_bounds__(256) void k_small(const float* __restrict__ soft) {
    __shared__ __align__(16) __nv_bfloat16 rn_s[32][136];  // [k=i local][m=d local], +8 pad
    __shared__ __align__(16) __nv_bfloat16 sn_s[32][72];   // [k=i local][n], +8 pad

    int mtile = blockIdx.x;   // 0..7  -> d range
    int split = blockIdx.y;   // 0..7  -> i range
    int dbase = mtile * 128;
    int tid = threadIdx.x, lane = tid & 31, wid = tid >> 5;
    int wd = wid & 3, wn = wid >> 2;   // warp tile: 32 d x 32 n

    float acc[2][4][4];
    #pragma unroll
    for (int a = 0; a < 2; a++)
        #pragma unroll
        for (int b = 0; b < 4; b++)
            #pragma unroll
            for (int c = 0; c < 4; c++) acc[a][b][c] = 0.f;

    for (int ks = 0; ks < KCH / 32; ks++) {
        int i0 = split * KCH + ks * 32;
        // load rn tile [32 i][128 d]
        #pragma unroll
        for (int j = 0; j < 2; j++) {
            int idx = tid + 256 * j;       // 0..511
            int row = idx >> 4, seg = idx & 15;
            *(uint4*)&rn_s[row][seg * 8] =
                *(const uint4*)(g_rn + (size_t)(i0 + row) * D_SZ + dbase + seg * 8);
        }
        // build [soft | onehot] tile [32 i][64 n] in bf16
        #pragma unroll
        for (int j = 0; j < 8; j++) {
            int idx = tid + 256 * j;       // 0..2047
            int i = idx >> 6, n = idx & 63;
            float v = (n < 32) ? soft[(size_t)(i0 + i) * C_SZ + n]
                               : ((g_labels[i0 + i] == (n - 32)) ? 1.0f : 0.0f);
            sn_s[i][n] = __float2bfloat16(v);
        }
        __syncthreads();

        unsigned a[2][2][4];
        #pragma unroll
        for (int mi = 0; mi < 2; mi++)
            #pragma unroll
            for (int kg = 0; kg < 2; kg++) {
                int krow = kg * 16 + (lane & 7) + ((lane >> 4) << 3);
                int mcol = wd * 32 + mi * 16 + ((lane >> 3) & 1) * 8;
                ldm_x4_t(smem_u32(&rn_s[krow][mcol]),
                         a[mi][kg][0], a[mi][kg][1], a[mi][kg][2], a[mi][kg][3]);
            }
        unsigned b[4][2][2];
        #pragma unroll
        for (int ni = 0; ni < 4; ni++)
            #pragma unroll
            for (int kg = 0; kg < 2; kg++) {
                int krow = kg * 16 + (lane & 15);
                ldm_x2_t(smem_u32(&sn_s[krow][wn * 32 + ni * 8]),
                         b[ni][kg][0], b[ni][kg][1]);
            }
        #pragma unroll
        for (int kg = 0; kg < 2; kg++)
            #pragma unroll
            for (int mi = 0; mi < 2; mi++)
                #pragma unroll
                for (int ni = 0; ni < 4; ni++)
                    mma16816(acc[mi][ni][0], acc[mi][ni][1], acc[mi][ni][2], acc[mi][ni][3],
                             a[mi][kg][0], a[mi][kg][1], a[mi][kg][2], a[mi][kg][3],
                             b[ni][kg][0], b[ni][kg][1]);
        __syncthreads();
    }

    // store partials (plain STG, no atomics)
    #pragma unroll
    for (int mi = 0; mi < 2; mi++)
        #pragma unroll
        for (int ni = 0; ni < 4; ni++)
            #pragma unroll
            for (int r = 0; r < 4; r++) {
                int row = (lane >> 2) + (r >> 1) * 8;
                int col = (lane & 3) * 2 + (r & 1);
                int dl = wd * 32 + mi * 16 + row;
                int n  = wn * 32 + ni * 8 + col;
                g_part[((size_t)(split * 8 + mtile) * 128 + dl) * NSM + n] = acc[mi][ni][r];
            }
}

// main pass: rowsumE[i] = sum_{j!=i} exp(Z_ij), triangular 128x128 tiles, bf16 mma
__global__ __launch_bounds__(256) void k_gemm() {
    __shared__ __align__(16) __nv_bfloat16 sA[2][BM][SK];
    __shared__ __align__(16) __nv_bfloat16 sB[2][BN][SK];
    __shared__ float rowbuf[BM];
    __shared__ float colbuf[BN];

    int idx = blockIdx.x;
    int I = 0;
    while (idx >= (TTOT - I)) { idx -= (TTOT - I); ++I; }
    int J = I + idx;
    bool diag = (I == J);

    int tid = threadIdx.x;
    int wid = tid >> 5, lane = tid & 31;
    int wm = wid & 1, wn = wid >> 1;

    if (tid < BM) { rowbuf[tid] = 0.f; colbuf[tid] = 0.f; }

    const __nv_bfloat16* gA = g_rn + (size_t)I * BM * D_SZ;
    const __nv_bfloat16* gB = g_rn + (size_t)J * BN * D_SZ;

    int lrow = tid >> 1, lseg = tid & 1;

    float acc[4][4][4];
    #pragma unroll
    for (int a = 0; a < 4; a++)
        #pragma unroll
        for (int b = 0; b < 4; b++)
            #pragma unroll
            for (int c = 0; c < 4; c++) acc[a][b][c] = 0.f;

    {
        const uint4* pa = (const uint4*)(gA + (size_t)lrow * D_SZ) + lseg * 2;
        const uint4* pb = (const uint4*)(gB + (size_t)lrow * D_SZ) + lseg * 2;
        *(uint4*)&sA[0][lrow][lseg * 16]     = pa[0];
        *(uint4*)&sA[0][lrow][lseg * 16 + 8] = pa[1];
        *(uint4*)&sB[0][lrow][lseg * 16]     = pb[0];
        *(uint4*)&sB[0][lrow][lseg * 16 + 8] = pb[1];
    }
    __syncthreads();

    const int KT = D_SZ / BK;
    for (int kt = 0; kt < KT; ++kt) {
        uint4 ra0, ra1, rb0, rb1;
        if (kt + 1 < KT) {
            const uint4* pa = (const uint4*)(gA + (size_t)lrow * D_SZ + (kt + 1) * BK) + lseg * 2;
            const uint4* pb = (const uint4*)(gB + (size_t)lrow * D_SZ + (kt + 1) * BK) + lseg * 2;
            ra0 = pa[0]; ra1 = pa[1]; rb0 = pb[0]; rb1 = pb[1];
        }
        int buf = kt & 1;
        #pragma unroll
        for (int s = 0; s < 2; s++) {
            unsigned a[4][4], b[4][2];
            #pragma unroll
            for (int mi = 0; mi < 4; mi++) {
                unsigned addr = smem_u32(&sA[buf][wm * 64 + mi * 16 + (lane & 15)][s * 16 + (lane >> 4) * 8]);
                ldm_x4(addr, a[mi][0], a[mi][1], a[mi][2], a[mi][3]);
            }
            #pragma unroll
            for (int ni = 0; ni < 4; ni++) {
                unsigned addr = smem_u32(&sB[buf][wn * 32 + ni * 8 + (lane & 7)][s * 16 + ((lane >> 3) & 1) * 8]);
                ldm_x2(addr, b[ni][0], b[ni][1]);
            }
            #pragma unroll
            for (int mi = 0; mi < 4; mi++)
                #pragma unroll
                for (int ni = 0; ni < 4; ni++)
                    mma16816(acc[mi][ni][0], acc[mi][ni][1], acc[mi][ni][2], acc[mi][ni][3],
                             a[mi][0], a[mi][1], a[mi][2], a[mi][3], b[ni][0], b[ni][1]);
        }
        if (kt + 1 < KT) {
            int nb = buf ^ 1;
            *(uint4*)&sA[nb][lrow][lseg * 16]     = ra0;
            *(uint4*)&sA[nb][lrow][lseg * 16 + 8] = ra1;
            *(uint4*)&sB[nb][lrow][lseg * 16]     = rb0;
            *(uint4*)&sB[nb][lrow][lseg * 16 + 8] = rb1;
        }
        __syncthreads();
    }

    int g = lane >> 2, t = lane & 3;
    int rbase = wm * 64, cbase = wn * 32;
    float colp[4][2];
    #pragma unroll
    for (int ni = 0; ni < 4; ni++) { colp[ni][0] = 0.f; colp[ni][1] = 0.f; }

    #pragma unroll
    for (int mi = 0; mi < 4; mi++) {
        float r0 = 0.f, r1 = 0.f;
        #pragma unroll
        for (int ni = 0; ni < 4; ni++) {
            float e0 = __expf(acc[mi][ni][0] * TEMP_INV);
            float e1 = __expf(acc[mi][ni][1] * TEMP_INV);
            float e2 = __expf(acc[mi][ni][2] * TEMP_INV);
            float e3 = __expf(acc[mi][ni][3] * TEMP_INV);
            if (diag) {
                int r = rbase + mi * 16 + g, c = cbase + ni * 8 + t * 2;
                if (r == c)     e0 = 0.f;
                if (r == c + 1) e1 = 0.f;
                if (r + 8 == c)     e2 = 0.f;
                if (r + 8 == c + 1) e3 = 0.f;
            }
            r0 += e0 + e1; r1 += e2 + e3;
            colp[ni][0] += e0 + e2; colp[ni][1] += e1 + e3;
        }
        r0 += __shfl_xor_sync(~0u, r0, 1); r0 += __shfl_xor_sync(~0u, r0, 2);
        r1 += __shfl_xor_sync(~0u, r1, 1); r1 += __shfl_xor_sync(~0u, r1, 2);
        if (t == 0) {
            atomicAdd(&rowbuf[rbase + mi * 16 + g],     r0);
            atomicAdd(&rowbuf[rbase + mi * 16 + g + 8], r1);
        }
    }
    if (!diag) {
        #pragma unroll
        for (int ni = 0; ni < 4; ni++) {
            #pragma unroll
            for (int p = 0; p < 2; p++) {
                float v = colp[ni][p];
                v += __shfl_xor_sync(~0u, v, 4);
                v += __shfl_xor_sync(~0u, v, 8);
                v += __shfl_xor_sync(~0u, v, 16);
                if (lane < 4) atomicAdd(&colbuf[cbase + ni * 8 + lane * 2 + p], v);
            }
        }
    }
    __syncthreads();
    if (tid < BM) {
        atomicAdd(&g_rowsumE[I * BM + tid], rowbuf[tid]);
        if (!diag) atomicAdd(&g_rowsumE[J * BN + tid], colbuf[tid]);
    }
}

// reduce split-k partials -> sum of squares of U and M
__global__ void k_sumsq() {
    int idx = blockIdx.x * 256 + threadIdx.x;   // grid 256 blocks covers 1024*64
    float su = 0.f, sm = 0.f;
    if (idx < D_SZ * NSM) {
        int d = idx >> 6, n = idx & 63;
        int mt = d >> 7, dl = d & 127;
        float s = 0.f;
        #pragma unroll
        for (int sp = 0; sp < KSPLIT; sp++)
            s += g_part[((size_t)(sp * 8 + mt) * 128 + dl) * NSM + n];
        if (n < C_SZ) su = s * s; else sm = s * s;
    }
    #pragma unroll
    for (int o = 16; o; o >>= 1) { su += __shfl_xor_sync(~0u, su, o); sm += __shfl_xor_sync(~0u, sm, o); }
    __shared__ float rs[8], rm[8];
    if ((threadIdx.x & 31) == 0) { rs[threadIdx.x >> 5] = su; rm[threadIdx.x >> 5] = sm; }
    __syncthreads();
    if (threadIdx.x < 8) {
        float a = rs[threadIdx.x], b = rm[threadIdx.x];
        #pragma unroll
        for (int o = 4; o; o >>= 1) { a += __shfl_xor_sync(0xff, a, o); b += __shfl_xor_sync(0xff, b, o); }
        if (threadIdx.x == 0) { atomicAdd(&g_sumU2, a); atomicAdd(&g_sumM2, b); }
    }
}

__global__ void k_rowterms(const float* __restrict__ soft, const void* pwp) {
    float pw = decode_pw(pwp);
    int i = blockIdx.x * blockDim.x + threadIdx.x;
    float term = 0.f;
    if (i < B_SZ) {
        int lbl = g_labels[i];
        float wsum = (float)(g_hist[lbl] - 1);
        const float* s = soft + (size_t)i * C_SZ;
        float d = 0.f;
        #pragma unroll
        for (int c = 0; c < C_SZ; c++) d += s[c] * g_Ssum[c];
        wsum += pw * d;
        term = wsum * logf(g_rowsumE[i]);
    }
    #pragma unroll
    for (int o = 16; o; o >>= 1) term += __shfl_xor_sync(~0u, term, o);
    __shared__ float red[8];
    if ((threadIdx.x & 31) == 0) red[threadIdx.x >> 5] = term;
    __syncthreads();
    if (threadIdx.x < 8) {
        float v = red[threadIdx.x];
        #pragma unroll
        for (int o = 4; o; o >>= 1) v += __shfl_xor_sync(0xff, v, o);
        if (threadIdx.x == 0) atomicAdd(&g_accLog, v);
    }
}

__global__ void k_out(float* out, const void* pwp) {
    float pw = decode_pw(pwp);
    float P  = (g_sumM2 - g_diagsum) * TEMP_INV;
    float SZ = g_sumU2 * TEMP_INV;
    out[0] = (g_accLog - P - pw * SZ) / (float)B_SZ;
}

// ---------------- launch ----------------
extern "C" void kernel_launch(void* const* d_in, const int* in_sizes, int n_in,
                              void* d_out, int out_size) {
    const float* reps = (const float*)d_in[0];
    const float* soft = (const float*)d_in[1];
    const int*   lblp = (const int*)d_in[2];
    const void*  pwp  = d_in[3];
    float* out = (float*)d_out;
    (void)in_sizes; (void)n_in; (void)out_size;

    k_zero<<<16, 256>>>();
    k_labels<<<16, 256>>>(lblp);
    k_norm<<<B_SZ, 256>>>(reps, soft);
    k_small<<<dim3(8, KSPLIT), 256>>>(soft);
    k_gemm<<<NPAIR, 256>>>();
    k_sumsq<<<256, 256>>>();
    k_rowterms<<<B_SZ / 256, 256>>>(soft, pwp);
    k_out<<<1, 1>>>(out, pwp);
}

// round 5
// speedup vs baseline: 1.8424x; 1.1215x over previous
#include <cuda_runtime.h>
#include <cuda_bf16.h>
#include <cuda_fp8.h>
#include <cstdint>

#define B_SZ 4096
#define D_SZ 1024
#define C_SZ 32
// bf16 rn scaled by sqrt(10*log2(e)); U/M sums divided by S2 later
#define RNSCALE 3.7982825500f
#define S2INV   (1.0f/14.4269504089f)
// fp8 rn scaled by 16; epilogue: exp(10 z) = 2^(acc * QC), QC = 10*log2(e)/256
#define QSCALE  16.0f
#define QC      0.05635527503472513f

#define BM 128
#define BN 128
#define BKQ 64            // fp8 elements per k-chunk
#define SKQ 80            // padded row stride in bytes (64 data + 16 pad)
#define TTOT (B_SZ/BM)    // 32
#define NPAIR (TTOT*(TTOT+1)/2)  // 528

// small GEMM (U|M): RN^T [1024 x 4096] @ [soft | onehot] [4096 x 64]
#define KSPLIT 32
#define KCH (B_SZ/KSPLIT)   // 128
#define NSM 64

// ---------------- device scratch ----------------
__device__ __align__(128) __nv_bfloat16 g_rn[B_SZ * D_SZ];   // bf16, scale RNSCALE
__device__ __align__(128) uint8_t       g_rq[B_SZ * D_SZ];   // e4m3, scale QSCALE
__device__ float g_rowsumE[B_SZ];
__device__ float g_part[KSPLIT * 8 * 128 * NSM];   // 8MB split-k partials
__device__ float g_Ssum[C_SZ];
__device__ int   g_hist[C_SZ];
__device__ int   g_labels[B_SZ];
__device__ float g_diagsum;
__device__ float g_accLog;
__device__ float g_sumU2;
__device__ float g_sumM2;

// ---------------- helpers ----------------
__device__ __forceinline__ float decode_pw(const void* p) {
    int v0 = ((const int*)p)[0];
    if (v0 > 0 && v0 < (1 << 26)) return (float)v0;
    float f = __int_as_float(v0);
    if (f > 0.0f && f < 1e8f) return f;
    return 0.0f;
}
__device__ __forceinline__ unsigned smem_u32(const void* p) {
    return (unsigned)__cvta_generic_to_shared(p);
}
__device__ __forceinline__ float ex2f(float x) {
    float y; asm("ex2.approx.f32 %0, %1;" : "=f"(y) : "f"(x)); return y;
}
__device__ __forceinline__ void ldm_x4(unsigned addr, unsigned &r0, unsigned &r1, unsigned &r2, unsigned &r3) {
    asm volatile("ldmatrix.sync.aligned.m8n8.x4.shared.b16 {%0,%1,%2,%3}, [%4];"
                 : "=r"(r0), "=r"(r1), "=r"(r2), "=r"(r3) : "r"(addr));
}
__device__ __forceinline__ void ldm_x2(unsigned addr, unsigned &r0, unsigned &r1) {
    asm volatile("ldmatrix.sync.aligned.m8n8.x2.shared.b16 {%0,%1}, [%2];"
                 : "=r"(r0), "=r"(r1) : "r"(addr));
}
__device__ __forceinline__ void ldm_x4_t(unsigned addr, unsigned &r0, unsigned &r1, unsigned &r2, unsigned &r3) {
    asm volatile("ldmatrix.sync.aligned.m8n8.x4.trans.shared.b16 {%0,%1,%2,%3}, [%4];"
                 : "=r"(r0), "=r"(r1), "=r"(r2), "=r"(r3) : "r"(addr));
}
__device__ __forceinline__ void ldm_x2_t(unsigned addr, unsigned &r0, unsigned &r1) {
    asm volatile("ldmatrix.sync.aligned.m8n8.x2.trans.shared.b16 {%0,%1}, [%2];"
                 : "=r"(r0), "=r"(r1) : "r"(addr));
}
__device__ __forceinline__ void mma16816(float &c0, float &c1, float &c2, float &c3,
                                         unsigned a0, unsigned a1, unsigned a2, unsigned a3,
                                         unsigned b0, unsigned b1) {
    asm volatile("mma.sync.aligned.m16n8k16.row.col.f32.bf16.bf16.f32 "
                 "{%0,%1,%2,%3},{%4,%5,%6,%7},{%8,%9},{%0,%1,%2,%3};"
                 : "+f"(c0), "+f"(c1), "+f"(c2), "+f"(c3)
                 : "r"(a0), "r"(a1), "r"(a2), "r"(a3), "r"(b0), "r"(b1));
}
__device__ __forceinline__ void mma16832q(float &c0, float &c1, float &c2, float &c3,
                                          unsigned a0, unsigned a1, unsigned a2, unsigned a3,
                                          unsigned b0, unsigned b1) {
    asm volatile("mma.sync.aligned.m16n8k32.row.col.f32.e4m3.e4m3.f32 "
                 "{%0,%1,%2,%3},{%4,%5,%6,%7},{%8,%9},{%0,%1,%2,%3};"
                 : "+f"(c0), "+f"(c1), "+f"(c2), "+f"(c3)
                 : "r"(a0), "r"(a1), "r"(a2), "r"(a3), "r"(b0), "r"(b1));
}
__device__ __forceinline__ uint16_t fp8pair(float lo, float hi) {
    uint16_t r;   // PTX: first source -> upper byte, second -> lower byte
    asm("cvt.rn.satfinite.e4m3x2.f32 %0, %1, %2;" : "=h"(r) : "f"(hi), "f"(lo));
    return r;
}

// ---------------- kernels ----------------
__global__ void k_zero() {
    int i = blockIdx.x * 256 + threadIdx.x;
    if (i < B_SZ) g_rowsumE[i] = 0.f;
    if (i < C_SZ) { g_Ssum[i] = 0.f; g_hist[i] = 0; }
    if (i == 0) { g_diagsum = 0.f; g_accLog = 0.f; g_sumU2 = 0.f; g_sumM2 = 0.f; }
}

__global__ void k_labels(const int* __restrict__ p) {
    __shared__ int is64;
    if (threadIdx.x == 0) {
        int any = 0;
        #pragma unroll
        for (int i = 1; i < 128; i += 2) any |= p[i];
        is64 = (any == 0) ? 1 : 0;
    }
    __syncthreads();
    int s64 = is64;
    for (int i = blockIdx.x * blockDim.x + threadIdx.x; i < B_SZ; i += gridDim.x * blockDim.x)
        g_labels[i] = s64 ? p[2 * i] : p[i];
}

// one-pass normalize: bf16 (scale RNSCALE) + e4m3 (scale QSCALE)
__global__ __launch_bounds__(256) void k_norm(const float* __restrict__ reps, const float* __restrict__ soft) {
    int row = blockIdx.x;
    float4 v = ((const float4*)(reps + (size_t)row * D_SZ))[threadIdx.x];
    float ss = v.x * v.x + v.y * v.y + v.z * v.z + v.w * v.w;
    __shared__ float red[8];
    #pragma unroll
    for (int o = 16; o; o >>= 1) ss += __shfl_xor_sync(~0u, ss, o);
    if ((threadIdx.x & 31) == 0) red[threadIdx.x >> 5] = ss;
    __syncthreads();
    float sumsq = red[0] + red[1] + red[2] + red[3] + red[4] + red[5] + red[6] + red[7];
    float inv = 1.0f / fmaxf(sqrtf(sumsq), 1e-8f);
    float sc = inv * RNSCALE;
    __nv_bfloat162 p0 = __floats2bfloat162_rn(v.x * sc, v.y * sc);
    __nv_bfloat162 p1 = __floats2bfloat162_rn(v.z * sc, v.w * sc);
    uint2 pk; pk.x = *(uint32_t*)&p0; pk.y = *(uint32_t*)&p1;
    ((uint2*)(g_rn + (size_t)row * D_SZ))[threadIdx.x] = pk;
    float sq = inv * QSCALE;
    uint32_t q = (uint32_t)fp8pair(v.x * sq, v.y * sq)
               | ((uint32_t)fp8pair(v.z * sq, v.w * sq) << 16);
    ((uint32_t*)(g_rq + (size_t)row * D_SZ))[threadIdx.x] = q;
    if (threadIdx.x == 0) {
        atomicAdd(&g_diagsum, sumsq * inv * inv);
        atomicAdd(&g_hist[g_labels[row]], 1);
    }
    if (threadIdx.x < C_SZ) atomicAdd(&g_Ssum[threadIdx.x], soft[(size_t)row * C_SZ + threadIdx.x]);
}

// [U|M] = RN^T @ [soft | onehot] (scaled by RNSCALE), bf16 mma, split-k partials
__global__ __launch_bounds__(256) void k_small(const float* __restrict__ soft) {
    __shared__ __align__(16) __nv_bfloat16 rn_s[32][136];
    __shared__ __align__(16) __nv_bfloat16 sn_s[32][72];

    int mtile = blockIdx.x;   // 0..7
    int split = blockIdx.y;   // 0..31
    int dbase = mtile * 128;
    int tid = threadIdx.x, lane = tid & 31, wid = tid >> 5;
    int wd = wid & 3, wn = wid >> 2;

    float acc[2][4][4];
    #pragma unroll
    for (int a = 0; a < 2; a++)
        #pragma unroll
        for (int b = 0; b < 4; b++)
            #pragma unroll
            for (int c = 0; c < 4; c++) acc[a][b][c] = 0.f;

    for (int ks = 0; ks < KCH / 32; ks++) {
        int i0 = split * KCH + ks * 32;
        #pragma unroll
        for (int j = 0; j < 2; j++) {
            int idx = tid + 256 * j;
            int row = idx >> 4, seg = idx & 15;
            *(uint4*)&rn_s[row][seg * 8] =
                *(const uint4*)(g_rn + (size_t)(i0 + row) * D_SZ + dbase + seg * 8);
        }
        {
            int i = tid >> 3, q = tid & 7;
            float4 sv = *(const float4*)(soft + (size_t)(i0 + i) * C_SZ + q * 4);
            __nv_bfloat162 p0 = __floats2bfloat162_rn(sv.x, sv.y);
            __nv_bfloat162 p1 = __floats2bfloat162_rn(sv.z, sv.w);
            uint2 pk; pk.x = *(uint32_t*)&p0; pk.y = *(uint32_t*)&p1;
            *(uint2*)&sn_s[i][q * 4] = pk;
            int lbl = g_labels[i0 + i];
            int n0 = q * 4;
            #pragma unroll
            for (int k = 0; k < 4; k++)
                sn_s[i][32 + n0 + k] = __float2bfloat16((lbl == n0 + k) ? 1.0f : 0.0f);
        }
        __syncthreads();

        unsigned a[2][2][4];
        #pragma unroll
        for (int mi = 0; mi < 2; mi++)
            #pragma unroll
            for (int kg = 0; kg < 2; kg++) {
                int krow = kg * 16 + (lane & 7) + ((lane >> 4) << 3);
                int mcol = wd * 32 + mi * 16 + ((lane >> 3) & 1) * 8;
                ldm_x4_t(smem_u32(&rn_s[krow][mcol]),
                         a[mi][kg][0], a[mi][kg][1], a[mi][kg][2], a[mi][kg][3]);
            }
        unsigned b[4][2][2];
        #pragma unroll
        for (int ni = 0; ni < 4; ni++)
            #pragma unroll
            for (int kg = 0; kg < 2; kg++) {
                int krow = kg * 16 + (lane & 15);
                ldm_x2_t(smem_u32(&sn_s[krow][wn * 32 + ni * 8]),
                         b[ni][kg][0], b[ni][kg][1]);
            }
        #pragma unroll
        for (int kg = 0; kg < 2; kg++)
            #pragma unroll
            for (int mi = 0; mi < 2; mi++)
                #pragma unroll
                for (int ni = 0; ni < 4; ni++)
                    mma16816(acc[mi][ni][0], acc[mi][ni][1], acc[mi][ni][2], acc[mi][ni][3],
                             a[mi][kg][0], a[mi][kg][1], a[mi][kg][2], a[mi][kg][3],
                             b[ni][kg][0], b[ni][kg][1]);
        __syncthreads();
    }

    #pragma unroll
    for (int mi = 0; mi < 2; mi++)
        #pragma unroll
        for (int ni = 0; ni < 4; ni++)
            #pragma unroll
            for (int r = 0; r < 4; r++) {
                int row = (lane >> 2) + (r >> 1) * 8;
                int col = (lane & 3) * 2 + (r & 1);
                int dl = wd * 32 + mi * 16 + row;
                int n  = wn * 32 + ni * 8 + col;
                g_part[((size_t)(split * 8 + mtile) * 128 + dl) * NSM + n] = acc[mi][ni][r];
            }
}

// main pass: fp8 e4m3 mma, triangular 128x128 tiles, BK=64
__global__ __launch_bounds__(256) void k_gemm_q() {
    __shared__ __align__(16) uint8_t sA[2][BM * SKQ];
    __shared__ __align__(16) uint8_t sB[2][BN * SKQ];
    __shared__ float rowbuf[BM];
    __shared__ float colbuf[BN];

    int idx = blockIdx.x;
    int I = 0;
    while (idx >= (TTOT - I)) { idx -= (TTOT - I); ++I; }
    int J = I + idx;
    bool diag = (I == J);

    int tid = threadIdx.x;
    int wid = tid >> 5, lane = tid & 31;
    int wm = wid & 1, wn = wid >> 1;

    if (tid < BM) { rowbuf[tid] = 0.f; colbuf[tid] = 0.f; }

    const uint8_t* gA = g_rq + (size_t)I * BM * D_SZ;
    const uint8_t* gB = g_rq + (size_t)J * BN * D_SZ;

    int lrow = tid >> 1, lseg = tid & 1;   // 128 rows x 2 segs of 32B
    const uint8_t* pAr = gA + (size_t)lrow * D_SZ + lseg * 32;
    const uint8_t* pBr = gB + (size_t)lrow * D_SZ + lseg * 32;
    uint8_t* dAr = &sA[0][0] + lrow * SKQ + lseg * 32;
    uint8_t* dBr = &sB[0][0] + lrow * SKQ + lseg * 32;

    float acc[4][4][4];
    #pragma unroll
    for (int a = 0; a < 4; a++)
        #pragma unroll
        for (int b = 0; b < 4; b++)
            #pragma unroll
            for (int c = 0; c < 4; c++) acc[a][b][c] = 0.f;

    {   // preload k-tile 0
        *(uint4*)(dAr)      = *(const uint4*)(pAr);
        *(uint4*)(dAr + 16) = *(const uint4*)(pAr + 16);
        *(uint4*)(dBr)      = *(const uint4*)(pBr);
        *(uint4*)(dBr + 16) = *(const uint4*)(pBr + 16);
    }
    __syncthreads();

    const int KT = D_SZ / BKQ;   // 16
    for (int kt = 0; kt < KT; ++kt) {
        uint4 ra0, ra1, rb0, rb1;
        if (kt + 1 < KT) {
            ra0 = *(const uint4*)(pAr + (kt + 1) * BKQ);
            ra1 = *(const uint4*)(pAr + (kt + 1) * BKQ + 16);
            rb0 = *(const uint4*)(pBr + (kt + 1) * BKQ);
            rb1 = *(const uint4*)(pBr + (kt + 1) * BKQ + 16);
        }
        int buf = kt & 1;
        #pragma unroll
        for (int s = 0; s < 2; s++) {     // two k32 steps
            unsigned a[4][4], b[4][2];
            #pragma unroll
            for (int mi = 0; mi < 4; mi++) {
                unsigned addr = smem_u32(&sA[buf][(wm * 64 + mi * 16 + (lane & 15)) * SKQ
                                                 + s * 32 + (lane >> 4) * 16]);
                ldm_x4(addr, a[mi][0], a[mi][1], a[mi][2], a[mi][3]);
            }
            #pragma unroll
            for (int ni = 0; ni < 4; ni++) {
                unsigned addr = smem_u32(&sB[buf][(wn * 32 + ni * 8 + (lane & 7)) * SKQ
                                                 + s * 32 + ((lane >> 3) & 1) * 16]);
                ldm_x2(addr, b[ni][0], b[ni][1]);
            }
            #pragma unroll
            for (int mi = 0; mi < 4; mi++)
                #pragma unroll
                for (int ni = 0; ni < 4; ni++)
                    mma16832q(acc[mi][ni][0], acc[mi][ni][1], acc[mi][ni][2], acc[mi][ni][3],
                              a[mi][0], a[mi][1], a[mi][2], a[mi][3], b[ni][0], b[ni][1]);
        }
        if (kt + 1 < KT) {
            int nb = buf ^ 1;
            uint8_t* dA2 = &sA[nb][0] + lrow * SKQ + lseg * 32;
            uint8_t* dB2 = &sB[nb][0] + lrow * SKQ + lseg * 32;
            *(uint4*)(dA2)      = ra0;
            *(uint4*)(dA2 + 16) = ra1;
            *(uint4*)(dB2)      = rb0;
            *(uint4*)(dB2 + 16) = rb1;
        }
        __syncthreads();
    }

    // epilogue: e = 2^(acc*QC); row sums (I) and col sums (J)
    int g = lane >> 2, t = lane & 3;
    int rbase = wm * 64, cbase = wn * 32;
    float colp[4][2];
    #pragma unroll
    for (int ni = 0; ni < 4; ni++) { colp[ni][0] = 0.f; colp[ni][1] = 0.f; }

    #pragma unroll
    for (int mi = 0; mi < 4; mi++) {
        float r0 = 0.f, r1 = 0.f;
        #pragma unroll
        for (int ni = 0; ni < 4; ni++) {
            float e0 = ex2f(acc[mi][ni][0] * QC);
            float e1 = ex2f(acc[mi][ni][1] * QC);
            float e2 = ex2f(acc[mi][ni][2] * QC);
            float e3 = ex2f(acc[mi][ni][3] * QC);
            if (diag) {
                int r = rbase + mi * 16 + g, c = cbase + ni * 8 + t * 2;
                if (r == c)     e0 = 0.f;
                if (r == c + 1) e1 = 0.f;
                if (r + 8 == c)     e2 = 0.f;
                if (r + 8 == c + 1) e3 = 0.f;
            }
            r0 += e0 + e1; r1 += e2 + e3;
            colp[ni][0] += e0 + e2; colp[ni][1] += e1 + e3;
        }
        r0 += __shfl_xor_sync(~0u, r0, 1); r0 += __shfl_xor_sync(~0u, r0, 2);
        r1 += __shfl_xor_sync(~0u, r1, 1); r1 += __shfl_xor_sync(~0u, r1, 2);
        if (t == 0) {
            atomicAdd(&rowbuf[rbase + mi * 16 + g],     r0);
            atomicAdd(&rowbuf[rbase + mi * 16 + g + 8], r1);
        }
    }
    if (!diag) {
        #pragma unroll
        for (int ni = 0; ni < 4; ni++) {
            #pragma unroll
            for (int p = 0; p < 2; p++) {
                float v = colp[ni][p];
                v += __shfl_xor_sync(~0u, v, 4);
                v += __shfl_xor_sync(~0u, v, 8);
                v += __shfl_xor_sync(~0u, v, 16);
                if (lane < 4) atomicAdd(&colbuf[cbase + ni * 8 + lane * 2 + p], v);
            }
        }
    }
    __syncthreads();
    if (tid < BM) {
        atomicAdd(&g_rowsumE[I * BM + tid], rowbuf[tid]);
        if (!diag) atomicAdd(&g_rowsumE[J * BN + tid], colbuf[tid]);
    }
}

__global__ void k_sumsq() {
    int idx = blockIdx.x * 256 + threadIdx.x;
    float su = 0.f, sm = 0.f;
    if (idx < D_SZ * NSM) {
        int d = idx >> 6, n = idx & 63;
        int mt = d >> 7, dl = d & 127;
        float s = 0.f;
        #pragma unroll
        for (int sp = 0; sp < KSPLIT; sp++)
            s += g_part[((size_t)(sp * 8 + mt) * 128 + dl) * NSM + n];
        if (n < C_SZ) su = s * s; else sm = s * s;
    }
    #pragma unroll
    for (int o = 16; o; o >>= 1) { su += __shfl_xor_sync(~0u, su, o); sm += __shfl_xor_sync(~0u, sm, o); }
    __shared__ float rs[8], rm[8];
    if ((threadIdx.x & 31) == 0) { rs[threadIdx.x >> 5] = su; rm[threadIdx.x >> 5] = sm; }
    __syncthreads();
    if (threadIdx.x < 8) {
        float a = rs[threadIdx.x], b = rm[threadIdx.x];
        #pragma unroll
        for (int o = 4; o; o >>= 1) { a += __shfl_xor_sync(0xff, a, o); b += __shfl_xor_sync(0xff, b, o); }
        if (threadIdx.x == 0) { atomicAdd(&g_sumU2, a); atomicAdd(&g_sumM2, b); }
    }
}

__global__ void k_rowterms(const float* __restrict__ soft, const void* pwp) {
    float pw = decode_pw(pwp);
    int i = blockIdx.x * blockDim.x + threadIdx.x;
    float term = 0.f;
    if (i < B_SZ) {
        int lbl = g_labels[i];
        float wsum = (float)(g_hist[lbl] - 1);
        const float* s = soft + (size_t)i * C_SZ;
        float d = 0.f;
        #pragma unroll
        for (int c = 0; c < C_SZ; c++) d += s[c] * g_Ssum[c];
        wsum += pw * d;
        term = wsum * logf(g_rowsumE[i]);
    }
    #pragma unroll
    for (int o = 16; o; o >>= 1) term += __shfl_xor_sync(~0u, term, o);
    __shared__ float red[8];
    if ((threadIdx.x & 31) == 0) red[threadIdx.x >> 5] = term;
    __syncthreads();
    if (threadIdx.x < 8) {
        float v = red[threadIdx.x];
        #pragma unroll
        for (int o = 4; o; o >>= 1) v += __shfl_xor_sync(0xff, v, o);
        if (threadIdx.x == 0) atomicAdd(&g_accLog, v);
    }
}

__global__ void k_out(float* out, const void* pwp) {
    float pw = decode_pw(pwp);
    float P  = (g_sumM2 * S2INV - g_diagsum) * 10.0f;
    float SZ = (g_sumU2 * S2INV) * 10.0f;
    out[0] = (g_accLog - P - pw * SZ) / (float)B_SZ;
}

// ---------------- launch ----------------
extern "C" void kernel_launch(void* const* d_in, const int* in_sizes, int n_in,
                              void* d_out, int out_size) {
    const float* reps = (const float*)d_in[0];
    const float* soft = (const float*)d_in[1];
    const int*   lblp = (const int*)d_in[2];
    const void*  pwp  = d_in[3];
    float* out = (float*)d_out;
    (void)in_sizes; (void)n_in; (void)out_size;

    k_zero<<<16, 256>>>();
    k_labels<<<16, 256>>>(lblp);
    k_norm<<<B_SZ, 256>>>(reps, soft);
    k_small<<<dim3(8, KSPLIT), 256>>>(soft);
    k_gemm_q<<<NPAIR, 256>>>();
    k_sumsq<<<256, 256>>>();
    k_rowterms<<<B_SZ / 256, 256>>>(soft, pwp);
    k_out<<<1, 1>>>(out, pwp);
}

// round 8
// speedup vs baseline: 1.9102x; 1.0368x over previous
#include <cuda_runtime.h>
#include <cuda_bf16.h>
#include <cuda_fp8.h>
#include <cstdint>

#define B_SZ 4096
#define D_SZ 1024
#define C_SZ 32
// bf16 rn scaled by sqrt(10*log2(e)); U/M sums divided by S2 later
#define RNSCALE 3.7982825500f
#define S2INV   (1.0f/14.4269504089f)
// fp8 rn scaled by 16; epilogue: exp(10 z) = 2^(acc * QC), QC = 10*log2(e)/256
#define QSCALE  16.0f
#define QC      0.05635527503472513f

#define BM 128
#define BN 128
#define BKQ 64            // fp8 elements per k-chunk
#define SKQ 80            // padded row stride in bytes (64 data + 16 pad)
#define NST 4             // cp.async pipeline stages
#define TTOT (B_SZ/BM)    // 32
#define NPAIR (TTOT*(TTOT+1)/2)  // 528

// small GEMM (U|M): RN^T [1024 x 4096] @ [soft | onehot] [4096 x 64]
#define KSPLIT 64
#define KCH (B_SZ/KSPLIT)   // 64
#define NSM 64

// ---------------- device scratch ----------------
__device__ __align__(128) __nv_bfloat16 g_rn[B_SZ * D_SZ];   // bf16, scale RNSCALE
__device__ __align__(128) uint8_t       g_rq[B_SZ * D_SZ];   // e4m3, scale QSCALE
__device__ float g_rowsumE[B_SZ];
__device__ float g_part[KSPLIT * 8 * 128 * NSM];   // split-k partials (16MB)
__device__ float g_Ssum[C_SZ];
__device__ int   g_hist[C_SZ];
__device__ int   g_labels[B_SZ];
__device__ float g_diagsum;
__device__ float g_accLog;
__device__ float g_sumU2;
__device__ float g_sumM2;

// ---------------- helpers ----------------
__device__ __forceinline__ float decode_pw(const void* p) {
    int v0 = ((const int*)p)[0];
    if (v0 > 0 && v0 < (1 << 26)) return (float)v0;
    float f = __int_as_float(v0);
    if (f > 0.0f && f < 1e8f) return f;
    return 0.0f;
}
__device__ __forceinline__ unsigned smem_u32(const void* p) {
    return (unsigned)__cvta_generic_to_shared(p);
}
__device__ __forceinline__ float ex2f(float x) {
    float y; asm("ex2.approx.f32 %0, %1;" : "=f"(y) : "f"(x)); return y;
}
__device__ __forceinline__ void cp16(unsigned dst, const void* src) {
    asm volatile("cp.async.cg.shared.global [%0], [%1], 16;" :: "r"(dst), "l"(src));
}
#define CP_COMMIT() asm volatile("cp.async.commit_group;" ::: "memory")
#define CP_WAIT(n)  asm volatile("cp.async.wait_group %0;" :: "n"(n) : "memory")
__device__ __forceinline__ void ldm_x4(unsigned addr, unsigned &r0, unsigned &r1, unsigned &r2, unsigned &r3) {
    asm volatile("ldmatrix.sync.aligned.m8n8.x4.shared.b16 {%0,%1,%2,%3}, [%4];"
                 : "=r"(r0), "=r"(r1), "=r"(r2), "=r"(r3) : "r"(addr));
}
__device__ __forceinline__ void ldm_x2(unsigned addr, unsigned &r0, unsigned &r1) {
    asm volatile("ldmatrix.sync.aligned.m8n8.x2.shared.b16 {%0,%1}, [%2];"
                 : "=r"(r0), "=r"(r1) : "r"(addr));
}
__device__ __forceinline__ void ldm_x4_t(unsigned addr, unsigned &r0, unsigned &r1, unsigned &r2, unsigned &r3) {
    asm volatile("ldmatrix.sync.aligned.m8n8.x4.trans.shared.b16 {%0,%1,%2,%3}, [%4];"
                 : "=r"(r0), "=r"(r1), "=r"(r2), "=r"(r3) : "r"(addr));
}
__device__ __forceinline__ void ldm_x2_t(unsigned addr, unsigned &r0, unsigned &r1) {
    asm volatile("ldmatrix.sync.aligned.m8n8.x2.trans.shared.b16 {%0,%1}, [%2];"
                 : "=r"(r0), "=r"(r1) : "r"(addr));
}
__device__ __forceinline__ void mma16816(float &c0, float &c1, float &c2, float &c3,
                                         unsigned a0, unsigned a1, unsigned a2, unsigned a3,
                                         unsigned b0, unsigned b1) {
    asm volatile("mma.sync.aligned.m16n8k16.row.col.f32.bf16.bf16.f32 "
                 "{%0,%1,%2,%3},{%4,%5,%6,%7},{%8,%9},{%0,%1,%2,%3};"
                 : "+f"(c0), "+f"(c1), "+f"(c2), "+f"(c3)
                 : "r"(a0), "r"(a1), "r"(a2), "r"(a3), "r"(b0), "r"(b1));
}
__device__ __forceinline__ void mma16832q(float &c0, float &c1, float &c2, float &c3,
                                          unsigned a0, unsigned a1, unsigned a2, unsigned a3,
                                          unsigned b0, unsigned b1) {
    asm volatile("mma.sync.aligned.m16n8k32.row.col.f32.e4m3.e4m3.f32 "
                 "{%0,%1,%2,%3},{%4,%5,%6,%7},{%8,%9},{%0,%1,%2,%3};"
                 : "+f"(c0), "+f"(c1), "+f"(c2), "+f"(c3)
                 : "r"(a0), "r"(a1), "r"(a2), "r"(a3), "r"(b0), "r"(b1));
}
__device__ __forceinline__ uint16_t fp8pair(float lo, float hi) {
    uint16_t r;
    asm("cvt.rn.satfinite.e4m3x2.f32 %0, %1, %2;" : "=h"(r) : "f"(hi), "f"(lo));
    return r;
}

// ---------------- kernels ----------------
// fused zero + label decode
__global__ void k_init(const int* __restrict__ p) {
    __shared__ int is64;
    if (threadIdx.x == 0) {
        int any = 0;
        #pragma unroll
        for (int i = 1; i < 128; i += 2) any |= p[i];
        is64 = (any == 0) ? 1 : 0;
    }
    __syncthreads();
    int s64 = is64;
    int i = blockIdx.x * 256 + threadIdx.x;
    if (i < B_SZ) {
        g_rowsumE[i] = 0.f;
        g_labels[i] = s64 ? p[2 * i] : p[i];
    }
    if (i < C_SZ) { g_Ssum[i] = 0.f; g_hist[i] = 0; }
    if (i == 0) { g_diagsum = 0.f; g_accLog = 0.f; g_sumU2 = 0.f; g_sumM2 = 0.f; }
}

// one-pass normalize: bf16 (scale RNSCALE) + e4m3 (scale QSCALE)
__global__ __launch_bounds__(256) void k_norm(const float* __restrict__ reps, const float* __restrict__ soft) {
    int row = blockIdx.x;
    float4 v = ((const float4*)(reps + (size_t)row * D_SZ))[threadIdx.x];
    float ss = v.x * v.x + v.y * v.y + v.z * v.z + v.w * v.w;
    __shared__ float red[8];
    #pragma unroll
    for (int o = 16; o; o >>= 1) ss += __shfl_xor_sync(~0u, ss, o);
    if ((threadIdx.x & 31) == 0) red[threadIdx.x >> 5] = ss;
    __syncthreads();
    float sumsq = red[0] + red[1] + red[2] + red[3] + red[4] + red[5] + red[6] + red[7];
    float inv = 1.0f / fmaxf(sqrtf(sumsq), 1e-8f);
    float sc = inv * RNSCALE;
    __nv_bfloat162 p0 = __floats2bfloat162_rn(v.x * sc, v.y * sc);
    __nv_bfloat162 p1 = __floats2bfloat162_rn(v.z * sc, v.w * sc);
    uint2 pk; pk.x = *(uint32_t*)&p0; pk.y = *(uint32_t*)&p1;
    ((uint2*)(g_rn + (size_t)row * D_SZ))[threadIdx.x] = pk;
    float sq = inv * QSCALE;
    uint32_t q = (uint32_t)fp8pair(v.x * sq, v.y * sq)
               | ((uint32_t)fp8pair(v.z * sq, v.w * sq) << 16);
    ((uint32_t*)(g_rq + (size_t)row * D_SZ))[threadIdx.x] = q;
    if (threadIdx.x == 0) {
        atomicAdd(&g_diagsum, sumsq * inv * inv);
        atomicAdd(&g_hist[g_labels[row]], 1);
    }
    if (threadIdx.x < C_SZ) atomicAdd(&g_Ssum[threadIdx.x], soft[(size_t)row * C_SZ + threadIdx.x]);
}

// [U|M] = RN^T @ [soft | onehot] (scaled by RNSCALE), bf16 mma, split-k partials
__global__ __launch_bounds__(256) void k_small(const float* __restrict__ soft) {
    __shared__ __align__(16) __nv_bfloat16 rn_s[32][136];
    __shared__ __align__(16) __nv_bfloat16 sn_s[32][72];

    int mtile = blockIdx.x;   // 0..7
    int split = blockIdx.y;   // 0..KSPLIT-1
    int dbase = mtile * 128;
    int tid = threadIdx.x, lane = tid & 31, wid = tid >> 5;
    int wd = wid & 3, wn = wid >> 2;

    float acc[2][4][4];
    #pragma unroll
    for (int a = 0; a < 2; a++)
        #pragma unroll
        for (int b = 0; b < 4; b++)
            #pragma unroll
            for (int c = 0; c < 4; c++) acc[a][b][c] = 0.f;

    for (int ks = 0; ks < KCH / 32; ks++) {
        int i0 = split * KCH + ks * 32;
        #pragma unroll
        for (int j = 0; j < 2; j++) {
            int idx = tid + 256 * j;
            int row = idx >> 4, seg = idx & 15;
            *(uint4*)&rn_s[row][seg * 8] =
                *(const uint4*)(g_rn + (size_t)(i0 + row) * D_SZ + dbase + seg * 8);
        }
        {
            int i = tid >> 3, q = tid & 7;
            float4 sv = *(const float4*)(soft + (size_t)(i0 + i) * C_SZ + q * 4);
            __nv_bfloat162 p0 = __floats2bfloat162_rn(sv.x, sv.y);
            __nv_bfloat162 p1 = __floats2bfloat162_rn(sv.z, sv.w);
            uint2 pk; pk.x = *(uint32_t*)&p0; pk.y = *(uint32_t*)&p1;
            *(uint2*)&sn_s[i][q * 4] = pk;
            int lbl = g_labels[i0 + i];
            int n0 = q * 4;
            #pragma unroll
            for (int k = 0; k < 4; k++)
                sn_s[i][32 + n0 + k] = __float2bfloat16((lbl == n0 + k) ? 1.0f : 0.0f);
        }
        __syncthreads();

        unsigned a[2][2][4];
        #pragma unroll
        for (int mi = 0; mi < 2; mi++)
            #pragma unroll
            for (int kg = 0; kg < 2; kg++) {
                int krow = kg * 16 + (lane & 7) + ((lane >> 4) << 3);
                int mcol = wd * 32 + mi * 16 + ((lane >> 3) & 1) * 8;
                ldm_x4_t(smem_u32(&rn_s[krow][mcol]),
                         a[mi][kg][0], a[mi][kg][1], a[mi][kg][2], a[mi][kg][3]);
            }
        unsigned b[4][2][2];
        #pragma unroll
        for (int ni = 0; ni < 4; ni++)
            #pragma unroll
            for (int kg = 0; kg < 2; kg++) {
                int krow = kg * 16 + (lane & 15);
                ldm_x2_t(smem_u32(&sn_s[krow][wn * 32 + ni * 8]),
                         b[ni][kg][0], b[ni][kg][1]);
            }
        #pragma unroll
        for (int kg = 0; kg < 2; kg++)
            #pragma unroll
            for (int mi = 0; mi < 2; mi++)
                #pragma unroll
                for (int ni = 0; ni < 4; ni++)
                    mma16816(acc[mi][ni][0], acc[mi][ni][1], acc[mi][ni][2], acc[mi][ni][3],
                             a[mi][kg][0], a[mi][kg][1], a[mi][kg][2], a[mi][kg][3],
                             b[ni][kg][0], b[ni][kg][1]);
        __syncthreads();
    }

    #pragma unroll
    for (int mi = 0; mi < 2; mi++)
        #pragma unroll
        for (int ni = 0; ni < 4; ni++)
            #pragma unroll
            for (int r = 0; r < 4; r++) {
                int row = (lane >> 2) + (r >> 1) * 8;
                int col = (lane & 3) * 2 + (r & 1);
                int dl = wd * 32 + mi * 16 + row;
                int n  = wn * 32 + ni * 8 + col;
                g_part[((size_t)(split * 8 + mtile) * 128 + dl) * NSM + n] = acc[mi][ni][r];
            }
}

// main pass: fp8 e4m3 mma, triangular 128x128 tiles, 4-stage cp.async, 2 CTA/SM
__global__ __launch_bounds__(256, 2) void k_gemm_q() {
    __shared__ __align__(16) uint8_t sA[NST][BM * SKQ];
    __shared__ __align__(16) uint8_t sB[NST][BN * SKQ];
    __shared__ float rowbuf[BM];
    __shared__ float colbuf[BN];

    int idx = blockIdx.x;
    int I = 0;
    while (idx >= (TTOT - I)) { idx -= (TTOT - I); ++I; }
    int J = I + idx;
    bool diag = (I == J);

    int tid = threadIdx.x;
    int wid = tid >> 5, lane = tid & 31;
    int wm = wid & 1, wn = wid >> 1;

    if (tid < BM) { rowbuf[tid] = 0.f; colbuf[tid] = 0.f; }

    int lrow = tid >> 1, lseg = tid & 1;   // 128 rows x 2 segs of 32B
    const uint8_t* pAr = g_rq + (size_t)(I * BM + lrow) * D_SZ + lseg * 32;
    const uint8_t* pBr = g_rq + (size_t)(J * BN + lrow) * D_SZ + lseg * 32;
    unsigned dA = smem_u32(&sA[0][0]) + lrow * SKQ + lseg * 32;
    unsigned dB = smem_u32(&sB[0][0]) + lrow * SKQ + lseg * 32;

    float acc[4][4][4];
    #pragma unroll
    for (int a = 0; a < 4; a++)
        #pragma unroll
        for (int b = 0; b < 4; b++)
            #pragma unroll
            for (int c = 0; c < 4; c++) acc[a][b][c] = 0.f;

    const int KT = D_SZ / BKQ;   // 16
    // prologue: stages 0..NST-2
    #pragma unroll
    for (int p = 0; p < NST - 1; p++) {
        cp16(dA + p * (BM * SKQ),      pAr + p * BKQ);
        cp16(dA + p * (BM * SKQ) + 16, pAr + p * BKQ + 16);
        cp16(dB + p * (BN * SKQ),      pBr + p * BKQ);
        cp16(dB + p * (BN * SKQ) + 16, pBr + p * BKQ + 16);
        CP_COMMIT();
    }

    for (int kt = 0; kt < KT; ++kt) {
        int buf = kt & (NST - 1);
        CP_WAIT(NST - 2);
        __syncthreads();
        // issue load for stage kt+NST-1 into the stage consumed at iter kt-1
        int nk = kt + NST - 1;
        if (nk < KT) {
            int nb = nk & (NST - 1);
            cp16(dA + nb * (BM * SKQ),      pAr + nk * BKQ);
            cp16(dA + nb * (BM * SKQ) + 16, pAr + nk * BKQ + 16);
            cp16(dB + nb * (BN * SKQ),      pBr + nk * BKQ);
            cp16(dB + nb * (BN * SKQ) + 16, pBr + nk * BKQ + 16);
        }
        CP_COMMIT();
        #pragma unroll
        for (int s = 0; s < 2; s++) {     // two k32 steps
            unsigned a[4][4], b[4][2];
            #pragma unroll
            for (int mi = 0; mi < 4; mi++) {
                unsigned addr = smem_u32(&sA[buf][(wm * 64 + mi * 16 + (lane & 15)) * SKQ
                                                 + s * 32 + (lane >> 4) * 16]);
                ldm_x4(addr, a[mi][0], a[mi][1], a[mi][2], a[mi][3]);
            }
            #pragma unroll
            for (int ni = 0; ni < 4; ni++) {
                unsigned addr = smem_u32(&sB[buf][(wn * 32 + ni * 8 + (lane & 7)) * SKQ
                                                 + s * 32 + ((lane >> 3) & 1) * 16]);
                ldm_x2(addr, b[ni][0], b[ni][1]);
            }
            #pragma unroll
            for (int mi = 0; mi < 4; mi++)
                #pragma unroll
                for (int ni = 0; ni < 4; ni++)
                    mma16832q(acc[mi][ni][0], acc[mi][ni][1], acc[mi][ni][2], acc[mi][ni][3],
                              a[mi][0], a[mi][1], a[mi][2], a[mi][3], b[ni][0], b[ni][1]);
        }
        __syncthreads();
    }

    // epilogue: e = 2^(acc*QC); row sums (I) and col sums (J)
    int g = lane >> 2, t = lane & 3;
    int rbase = wm * 64, cbase = wn * 32;
    float colp[4][2];
    #pragma unroll
    for (int ni = 0; ni < 4; ni++) { colp[ni][0] = 0.f; colp[ni][1] = 0.f; }

    #pragma unroll
    for (int mi = 0; mi < 4; mi++) {
        float r0 = 0.f, r1 = 0.f;
        #pragma unroll
        for (int ni = 0; ni < 4; ni++) {
            float e0 = ex2f(acc[mi][ni][0] * QC);
            float e1 = ex2f(acc[mi][ni][1] * QC);
            float e2 = ex2f(acc[mi][ni][2] * QC);
            float e3 = ex2f(acc[mi][ni][3] * QC);
            if (diag) {
                int r = rbase + mi * 16 + g, c = cbase + ni * 8 + t * 2;
                if (r == c)     e0 = 0.f;
                if (r == c + 1) e1 = 0.f;
                if (r + 8 == c)     e2 = 0.f;
                if (r + 8 == c + 1) e3 = 0.f;
            }
            r0 += e0 + e1; r1 += e2 + e3;
            colp[ni][0] += e0 + e2; colp[ni][1] += e1 + e3;
        }
        r0 += __shfl_xor_sync(~0u, r0, 1); r0 += __shfl_xor_sync(~0u, r0, 2);
        r1 += __shfl_xor_sync(~0u, r1, 1); r1 += __shfl_xor_sync(~0u, r1, 2);
        if (t == 0) {
            atomicAdd(&rowbuf[rbase + mi * 16 + g],     r0);
            atomicAdd(&rowbuf[rbase + mi * 16 + g + 8], r1);
        }
    }
    if (!diag) {
        #pragma unroll
        for (int ni = 0; ni < 4; ni++) {
            #pragma unroll
            for (int p = 0; p < 2; p++) {
                float v = colp[ni][p];
                v += __shfl_xor_sync(~0u, v, 4);
                v += __shfl_xor_sync(~0u, v, 8);
                v += __shfl_xor_sync(~0u, v, 16);
                if (lane < 4) atomicAdd(&colbuf[cbase + ni * 8 + lane * 2 + p], v);
            }
        }
    }
    __syncthreads();
    if (tid < BM) {
        atomicAdd(&g_rowsumE[I * BM + tid], rowbuf[tid]);
        if (!diag) atomicAdd(&g_rowsumE[J * BN + tid], colbuf[tid]);
    }
}

// fused: blocks [0,256) reduce split-k partials; blocks [256,272) row terms
__global__ void k_tail(const float* __restrict__ soft, const void* pwp) {
    if (blockIdx.x < 256) {
        int idx = blockIdx.x * 256 + threadIdx.x;
        float su = 0.f, sm = 0.f;
        {
            int d = idx >> 6, n = idx & 63;
            int mt = d >> 7, dl = d & 127;
            float s = 0.f;
            #pragma unroll
            for (int sp = 0; sp < KSPLIT; sp++)
                s += g_part[((size_t)(sp * 8 + mt) * 128 + dl) * NSM + n];
            if (n < C_SZ) su = s * s; else sm = s * s;
        }
        #pragma unroll
        for (int o = 16; o; o >>= 1) { su += __shfl_xor_sync(~0u, su, o); sm += __shfl_xor_sync(~0u, sm, o); }
        __shared__ float rs[8], rm[8];
        if ((threadIdx.x & 31) == 0) { rs[threadIdx.x >> 5] = su; rm[threadIdx.x >> 5] = sm; }
        __syncthreads();
        if (threadIdx.x < 8) {
            float a = rs[threadIdx.x], b = rm[threadIdx.x];
            #pragma unroll
            for (int o = 4; o; o >>= 1) { a += __shfl_xor_sync(0xff, a, o); b += __shfl_xor_sync(0xff, b, o); }
            if (threadIdx.x == 0) { atomicAdd(&g_sumU2, a); atomicAdd(&g_sumM2, b); }
        }
    } else {
        float pw = decode_pw(pwp);
        int i = (blockIdx.x - 256) * 256 + threadIdx.x;
        float term = 0.f;
        {
            int lbl = g_labels[i];
            float wsum = (float)(g_hist[lbl] - 1);
            const float* s = soft + (size_t)i * C_SZ;
            float d = 0.f;
            #pragma unroll
            for (int c = 0; c < C_SZ; c++) d += s[c] * g_Ssum[c];
            wsum += pw * d;
            term = wsum * logf(g_rowsumE[i]);
        }
        #pragma unroll
        for (int o = 16; o; o >>= 1) term += __shfl_xor_sync(~0u, term, o);
        __shared__ float red[8];
        if ((threadIdx.x & 31) == 0) red[threadIdx.x >> 5] = term;
        __syncthreads();
        if (threadIdx.x < 8) {
            float v = red[threadIdx.x];
            #pragma unroll
            for (int o = 4; o; o >>= 1) v += __shfl_xor_sync(0xff, v, o);
            if (threadIdx.x == 0) atomicAdd(&g_accLog, v);
        }
    }
}

__global__ void k_out(float* out, const void* pwp) {
    float pw = decode_pw(pwp);
    float P  = (g_sumM2 * S2INV - g_diagsum) * 10.0f;
    float SZ = (g_sumU2 * S2INV) * 10.0f;
    out[0] = (g_accLog - P - pw * SZ) / (float)B_SZ;
}

// ---------------- launch ----------------
extern "C" void kernel_launch(void* const* d_in, const int* in_sizes, int n_in,
                              void* d_out, int out_size) {
    const float* reps = (const float*)d_in[0];
    const float* soft = (const float*)d_in[1];
    const int*   lblp = (const int*)d_in[2];
    const void*  pwp  = d_in[3];
    float* out = (float*)d_out;
    (void)in_sizes; (void)n_in; (void)out_size;

    k_init<<<16, 256>>>(lblp);
    k_norm<<<B_SZ, 256>>>(reps, soft);
    k_small<<<dim3(8, KSPLIT), 256>>>(soft);
    k_gemm_q<<<NPAIR, 256>>>();
    k_tail<<<272, 256>>>(soft, pwp);
    k_out<<<1, 1>>>(out, pwp);
}

// round 9
// speedup vs baseline: 2.0328x; 1.0642x over previous
#include <cuda_runtime.h>
#include <cuda_bf16.h>
#include <cuda_fp16.h>
#include <cuda_fp8.h>
#include <cstdint>

#define B_SZ 4096
#define D_SZ 1024
#define C_SZ 32
// bf16 rn scaled by sqrt(10*log2(e)); U/M sums divided by S2 later
#define RNSCALE 3.7982825500f
#define S2INV   (1.0f/14.4269504089f)
// fp8 rn scaled by 16; epilogue: exp(10 z) = 2^(acc * QC), QC = 10*log2(e)/256
#define QSCALE  16.0f
#define QC      0.05635527503472513f

#define BM 128
#define BN 128
#define BKQ 64            // fp8 elements per k-chunk
#define SKQ 80            // padded row stride in bytes (64 data + 16 pad)
#define NST 4             // cp.async pipeline stages
#define TTOT (B_SZ/BM)    // 32
#define NPAIR (TTOT*(TTOT+1)/2)  // 528

// small GEMM (U|M): RN^T [1024 x 4096] @ [soft | onehot] [4096 x 64]
#define KSPLIT 64
#define KCH (B_SZ/KSPLIT)   // 64
#define NSM 64

// ---------------- device scratch ----------------
__device__ __align__(128) __nv_bfloat16 g_rn[B_SZ * D_SZ];   // bf16, scale RNSCALE
__device__ __align__(128) uint8_t       g_rq[B_SZ * D_SZ];   // e4m3, scale QSCALE
__device__ float g_rowsumE[B_SZ];
__device__ float g_part[KSPLIT * 8 * 128 * NSM];   // split-k partials (16MB)
__device__ float g_Ssum[C_SZ];
__device__ int   g_hist[C_SZ];
__device__ int   g_labels[B_SZ];
__device__ float g_diagsum;
__device__ float g_accLog;
__device__ float g_sumU2;
__device__ float g_sumM2;

// ---------------- helpers ----------------
__device__ __forceinline__ float decode_pw(const void* p) {
    int v0 = ((const int*)p)[0];
    if (v0 > 0 && v0 < (1 << 26)) return (float)v0;
    float f = __int_as_float(v0);
    if (f > 0.0f && f < 1e8f) return f;
    return 0.0f;
}
__device__ __forceinline__ unsigned smem_u32(const void* p) {
    return (unsigned)__cvta_generic_to_shared(p);
}
__device__ __forceinline__ float ex2f(float x) {
    float y; asm("ex2.approx.f32 %0, %1;" : "=f"(y) : "f"(x)); return y;
}
__device__ __forceinline__ void cp16(unsigned dst, const void* src) {
    asm volatile("cp.async.cg.shared.global [%0], [%1], 16;" :: "r"(dst), "l"(src));
}
#define CP_COMMIT() asm volatile("cp.async.commit_group;" ::: "memory")
#define CP_WAIT(n)  asm volatile("cp.async.wait_group %0;" :: "n"(n) : "memory")
__device__ __forceinline__ void ldm_x4(unsigned addr, unsigned &r0, unsigned &r1, unsigned &r2, unsigned &r3) {
    asm volatile("ldmatrix.sync.aligned.m8n8.x4.shared.b16 {%0,%1,%2,%3}, [%4];"
                 : "=r"(r0), "=r"(r1), "=r"(r2), "=r"(r3) : "r"(addr));
}
__device__ __forceinline__ void ldm_x4_t(unsigned addr, unsigned &r0, unsigned &r1, unsigned &r2, unsigned &r3) {
    asm volatile("ldmatrix.sync.aligned.m8n8.x4.trans.shared.b16 {%0,%1,%2,%3}, [%4];"
                 : "=r"(r0), "=r"(r1), "=r"(r2), "=r"(r3) : "r"(addr));
}
__device__ __forceinline__ void ldm_x2_t(unsigned addr, unsigned &r0, unsigned &r1) {
    asm volatile("ldmatrix.sync.aligned.m8n8.x2.trans.shared.b16 {%0,%1}, [%2];"
                 : "=r"(r0), "=r"(r1) : "r"(addr));
}
__device__ __forceinline__ void mma16816(float &c0, float &c1, float &c2, float &c3,
                                         unsigned a0, unsigned a1, unsigned a2, unsigned a3,
                                         unsigned b0, unsigned b1) {
    asm volatile("mma.sync.aligned.m16n8k16.row.col.f32.bf16.bf16.f32 "
                 "{%0,%1,%2,%3},{%4,%5,%6,%7},{%8,%9},{%0,%1,%2,%3};"
                 : "+f"(c0), "+f"(c1), "+f"(c2), "+f"(c3)
                 : "r"(a0), "r"(a1), "r"(a2), "r"(a3), "r"(b0), "r"(b1));
}
// fp8 mma with f16 accumulator (full-rate path)
__device__ __forceinline__ void mma16832h(unsigned &c0, unsigned &c1,
                                          unsigned a0, unsigned a1, unsigned a2, unsigned a3,
                                          unsigned b0, unsigned b1) {
    asm volatile("mma.sync.aligned.m16n8k32.row.col.f16.e4m3.e4m3.f16 "
                 "{%0,%1},{%2,%3,%4,%5},{%6,%7},{%0,%1};"
                 : "+r"(c0), "+r"(c1)
                 : "r"(a0), "r"(a1), "r"(a2), "r"(a3), "r"(b0), "r"(b1));
}
__device__ __forceinline__ uint16_t fp8pair(float lo, float hi) {
    uint16_t r;
    asm("cvt.rn.satfinite.e4m3x2.f32 %0, %1, %2;" : "=h"(r) : "f"(hi), "f"(lo));
    return r;
}

// ---------------- kernels ----------------
// fused zero + label decode
__global__ void k_init(const int* __restrict__ p) {
    __shared__ int is64;
    if (threadIdx.x == 0) {
        int any = 0;
        #pragma unroll
        for (int i = 1; i < 128; i += 2) any |= p[i];
        is64 = (any == 0) ? 1 : 0;
    }
    __syncthreads();
    int s64 = is64;
    int i = blockIdx.x * 256 + threadIdx.x;
    if (i < B_SZ) {
        g_rowsumE[i] = 0.f;
        g_labels[i] = s64 ? p[2 * i] : p[i];
    }
    if (i < C_SZ) { g_Ssum[i] = 0.f; g_hist[i] = 0; }
    if (i == 0) { g_diagsum = 0.f; g_accLog = 0.f; g_sumU2 = 0.f; g_sumM2 = 0.f; }
}

// one-pass normalize: bf16 (scale RNSCALE) + e4m3 (scale QSCALE)
__global__ __launch_bounds__(256) void k_norm(const float* __restrict__ reps, const float* __restrict__ soft) {
    int row = blockIdx.x;
    float4 v = ((const float4*)(reps + (size_t)row * D_SZ))[threadIdx.x];
    float ss = v.x * v.x + v.y * v.y + v.z * v.z + v.w * v.w;
    __shared__ float red[8];
    #pragma unroll
    for (int o = 16; o; o >>= 1) ss += __shfl_xor_sync(~0u, ss, o);
    if ((threadIdx.x & 31) == 0) red[threadIdx.x >> 5] = ss;
    __syncthreads();
    float sumsq = red[0] + red[1] + red[2] + red[3] + red[4] + red[5] + red[6] + red[7];
    float inv = 1.0f / fmaxf(sqrtf(sumsq), 1e-8f);
    float sc = inv * RNSCALE;
    __nv_bfloat162 p0 = __floats2bfloat162_rn(v.x * sc, v.y * sc);
    __nv_bfloat162 p1 = __floats2bfloat162_rn(v.z * sc, v.w * sc);
    uint2 pk; pk.x = *(uint32_t*)&p0; pk.y = *(uint32_t*)&p1;
    ((uint2*)(g_rn + (size_t)row * D_SZ))[threadIdx.x] = pk;
    float sq = inv * QSCALE;
    uint32_t q = (uint32_t)fp8pair(v.x * sq, v.y * sq)
               | ((uint32_t)fp8pair(v.z * sq, v.w * sq) << 16);
    ((uint32_t*)(g_rq + (size_t)row * D_SZ))[threadIdx.x] = q;
    if (threadIdx.x == 0) {
        atomicAdd(&g_diagsum, sumsq * inv * inv);
        atomicAdd(&g_hist[g_labels[row]], 1);
    }
    if (threadIdx.x < C_SZ) atomicAdd(&g_Ssum[threadIdx.x], soft[(size_t)row * C_SZ + threadIdx.x]);
}

// [U|M] = RN^T @ [soft | onehot] (scaled by RNSCALE), bf16 mma, split-k partials
__global__ __launch_bounds__(256) void k_small(const float* __restrict__ soft) {
    __shared__ __align__(16) __nv_bfloat16 rn_s[32][136];
    __shared__ __align__(16) __nv_bfloat16 sn_s[32][72];

    int mtile = blockIdx.x;   // 0..7
    int split = blockIdx.y;   // 0..KSPLIT-1
    int dbase = mtile * 128;
    int tid = threadIdx.x, lane = tid & 31, wid = tid >> 5;
    int wd = wid & 3, wn = wid >> 2;

    float acc[2][4][4];
    #pragma unroll
    for (int a = 0; a < 2; a++)
        #pragma unroll
        for (int b = 0; b < 4; b++)
            #pragma unroll
            for (int c = 0; c < 4; c++) acc[a][b][c] = 0.f;

    for (int ks = 0; ks < KCH / 32; ks++) {
        int i0 = split * KCH + ks * 32;
        #pragma unroll
        for (int j = 0; j < 2; j++) {
            int idx = tid + 256 * j;
            int row = idx >> 4, seg = idx & 15;
            *(uint4*)&rn_s[row][seg * 8] =
                *(const uint4*)(g_rn + (size_t)(i0 + row) * D_SZ + dbase + seg * 8);
        }
        {
            int i = tid >> 3, q = tid & 7;
            float4 sv = *(const float4*)(soft + (size_t)(i0 + i) * C_SZ + q * 4);
            __nv_bfloat162 p0 = __floats2bfloat162_rn(sv.x, sv.y);
            __nv_bfloat162 p1 = __floats2bfloat162_rn(sv.z, sv.w);
            uint2 pk; pk.x = *(uint32_t*)&p0; pk.y = *(uint32_t*)&p1;
            *(uint2*)&sn_s[i][q * 4] = pk;
            int lbl = g_labels[i0 + i];
            int n0 = q * 4;
            #pragma unroll
            for (int k = 0; k < 4; k++)
                sn_s[i][32 + n0 + k] = __float2bfloat16((lbl == n0 + k) ? 1.0f : 0.0f);
        }
        __syncthreads();

        unsigned a[2][2][4];
        #pragma unroll
        for (int mi = 0; mi < 2; mi++)
            #pragma unroll
            for (int kg = 0; kg < 2; kg++) {
                int krow = kg * 16 + (lane & 7) + ((lane >> 4) << 3);
                int mcol = wd * 32 + mi * 16 + ((lane >> 3) & 1) * 8;
                ldm_x4_t(smem_u32(&rn_s[krow][mcol]),
                         a[mi][kg][0], a[mi][kg][1], a[mi][kg][2], a[mi][kg][3]);
            }
        unsigned b[4][2][2];
        #pragma unroll
        for (int ni = 0; ni < 4; ni++)
            #pragma unroll
            for (int kg = 0; kg < 2; kg++) {
                int krow = kg * 16 + (lane & 15);
                ldm_x2_t(smem_u32(&sn_s[krow][wn * 32 + ni * 8]),
                         b[ni][kg][0], b[ni][kg][1]);
            }
        #pragma unroll
        for (int kg = 0; kg < 2; kg++)
            #pragma unroll
            for (int mi = 0; mi < 2; mi++)
                #pragma unroll
                for (int ni = 0; ni < 4; ni++)
                    mma16816(acc[mi][ni][0], acc[mi][ni][1], acc[mi][ni][2], acc[mi][ni][3],
                             a[mi][kg][0], a[mi][kg][1], a[mi][kg][2], a[mi][kg][3],
                             b[ni][kg][0], b[ni][kg][1]);
        __syncthreads();
    }

    #pragma unroll
    for (int mi = 0; mi < 2; mi++)
        #pragma unroll
        for (int ni = 0; ni < 4; ni++)
            #pragma unroll
            for (int r = 0; r < 4; r++) {
                int row = (lane >> 2) + (r >> 1) * 8;
                int col = (lane & 3) * 2 + (r & 1);
                int dl = wd * 32 + mi * 16 + row;
                int n  = wn * 32 + ni * 8 + col;
                g_part[((size_t)(split * 8 + mtile) * 128 + dl) * NSM + n] = acc[mi][ni][r];
            }
}

// fragment/mma macros for the main fp8 kernel
#define LD_ALL(db, stg, s) do {                                                   \
    unsigned _ab = aBase + (unsigned)(stg) * (BM * SKQ) + aoff0 + (s) * 32;       \
    unsigned _bb = bBase + (unsigned)(stg) * (BN * SKQ) + boff0 + (s) * 32;       \
    ldm_x4(_ab,            fa[db][0][0], fa[db][0][1], fa[db][0][2], fa[db][0][3]); \
    ldm_x4(_ab + 16 * SKQ, fa[db][1][0], fa[db][1][1], fa[db][1][2], fa[db][1][3]); \
    ldm_x4(_ab + 32 * SKQ, fa[db][2][0], fa[db][2][1], fa[db][2][2], fa[db][2][3]); \
    ldm_x4(_ab + 48 * SKQ, fa[db][3][0], fa[db][3][1], fa[db][3][2], fa[db][3][3]); \
    ldm_x4(_bb,            fb[db][0][0], fb[db][0][1], fb[db][1][0], fb[db][1][1]); \
    ldm_x4(_bb + 16 * SKQ, fb[db][2][0], fb[db][2][1], fb[db][3][0], fb[db][3][1]); \
} while (0)

#define MMA_ALL(db) do {                                                          \
    _Pragma("unroll")                                                             \
    for (int mi = 0; mi < 4; mi++)                                                \
        _Pragma("unroll")                                                         \
        for (int ni = 0; ni < 4; ni++)                                            \
            mma16832h(acc[mi][ni][0], acc[mi][ni][1],                             \
                      fa[db][mi][0], fa[db][mi][1], fa[db][mi][2], fa[db][mi][3], \
                      fb[db][ni][0], fb[db][ni][1]);                              \
} while (0)

// main pass: fp8 e4m3 mma (f16 acc), triangular 128x128 tiles,
// 4-stage cp.async + double-buffered fragments, 2 CTA/SM
__global__ __launch_bounds__(256, 2) void k_gemm_q() {
    __shared__ __align__(16) uint8_t sA[NST][BM * SKQ];
    __shared__ __align__(16) uint8_t sB[NST][BN * SKQ];
    __shared__ float rowbuf[BM];
    __shared__ float colbuf[BN];

    int idx = blockIdx.x;
    int I = 0;
    while (idx >= (TTOT - I)) { idx -= (TTOT - I); ++I; }
    int J = I + idx;
    bool diag = (I == J);

    int tid = threadIdx.x;
    int wid = tid >> 5, lane = tid & 31;
    int wm = wid & 1, wn = wid >> 1;

    if (tid < BM) { rowbuf[tid] = 0.f; colbuf[tid] = 0.f; }

    int lrow = tid >> 1, lseg = tid & 1;   // 128 rows x 2 segs of 32B
    const uint8_t* pAr = g_rq + (size_t)(I * BM + lrow) * D_SZ + lseg * 32;
    const uint8_t* pBr = g_rq + (size_t)(J * BN + lrow) * D_SZ + lseg * 32;
    unsigned dA = smem_u32(&sA[0][0]) + lrow * SKQ + lseg * 32;
    unsigned dB = smem_u32(&sB[0][0]) + lrow * SKQ + lseg * 32;

    const unsigned aBase = smem_u32(&sA[0][0]);
    const unsigned bBase = smem_u32(&sB[0][0]);
    const unsigned aoff0 = (unsigned)((wm * 64 + (lane & 15)) * SKQ + (lane >> 4) * 16);
    const unsigned boff0 = (unsigned)((wn * 32 + ((lane >> 4) << 3) + (lane & 7)) * SKQ
                                      + (((lane >> 3) & 1) << 4));

    unsigned acc[4][4][2];
    #pragma unroll
    for (int a = 0; a < 4; a++)
        #pragma unroll
        for (int b = 0; b < 4; b++) { acc[a][b][0] = 0u; acc[a][b][1] = 0u; }

    const int KT = D_SZ / BKQ;   // 16
    // prologue: stages 0..NST-2
    #pragma unroll
    for (int p = 0; p < NST - 1; p++) {
        cp16(dA + p * (BM * SKQ),      pAr + p * BKQ);
        cp16(dA + p * (BM * SKQ) + 16, pAr + p * BKQ + 16);
        cp16(dB + p * (BN * SKQ),      pBr + p * BKQ);
        cp16(dB + p * (BN * SKQ) + 16, pBr + p * BKQ + 16);
        CP_COMMIT();
    }

    unsigned fa[2][4][4], fb[2][4][2];
    CP_WAIT(NST - 2);
    __syncthreads();
    LD_ALL(0, 0, 0);

    #pragma unroll 4
    for (int kt = 0; kt < KT; ++kt) {
        int buf = kt & (NST - 1);
        CP_WAIT(1);                 // stages <= kt+1 resident
        __syncthreads();
        int nk = kt + NST - 1;
        if (nk < KT) {
            int nb = nk & (NST - 1);
            cp16(dA + nb * (BM * SKQ),      pAr + nk * BKQ);
            cp16(dA + nb * (BM * SKQ) + 16, pAr + nk * BKQ + 16);
            cp16(dB + nb * (BN * SKQ),      pBr + nk * BKQ);
            cp16(dB + nb * (BN * SKQ) + 16, pBr + nk * BKQ + 16);
        }
        CP_COMMIT();
        // s=0: prefetch s=1 frags, then 16 mma on s=0 frags
        LD_ALL(1, buf, 1);
        MMA_ALL(0);
        // s=1: prefetch next kt's s=0 frags, then 16 mma on s=1 frags
        if (kt + 1 < KT) LD_ALL(0, (kt + 1) & (NST - 1), 0);
        MMA_ALL(1);
    }

    // epilogue: e = 2^(acc*QC); row sums (I) and col sums (J)
    int g = lane >> 2, t = lane & 3;
    int rbase = wm * 64, cbase = wn * 32;
    float colp[4][2];
    #pragma unroll
    for (int ni = 0; ni < 4; ni++) { colp[ni][0] = 0.f; colp[ni][1] = 0.f; }

    #pragma unroll
    for (int mi = 0; mi < 4; mi++) {
        float r0 = 0.f, r1 = 0.f;
        #pragma unroll
        for (int ni = 0; ni < 4; ni++) {
            float2 f0 = __half22float2(*(__half2*)&acc[mi][ni][0]);   // row g,   cols t2,t2+1
            float2 f1 = __half22float2(*(__half2*)&acc[mi][ni][1]);   // row g+8, cols t2,t2+1
            float e0 = ex2f(f0.x * QC);
            float e1 = ex2f(f0.y * QC);
            float e2 = ex2f(f1.x * QC);
            float e3 = ex2f(f1.y * QC);
            if (diag) {
                int r = rbase + mi * 16 + g, c = cbase + ni * 8 + t * 2;
                if (r == c)     e0 = 0.f;
                if (r == c + 1) e1 = 0.f;
                if (r + 8 == c)     e2 = 0.f;
                if (r + 8 == c + 1) e3 = 0.f;
            }
            r0 += e0 + e1; r1 += e2 + e3;
            colp[ni][0] += e0 + e2; colp[ni][1] += e1 + e3;
        }
        r0 += __shfl_xor_sync(~0u, r0, 1); r0 += __shfl_xor_sync(~0u, r0, 2);
        r1 += __shfl_xor_sync(~0u, r1, 1); r1 += __shfl_xor_sync(~0u, r1, 2);
        if (t == 0) {
            atomicAdd(&rowbuf[rbase + mi * 16 + g],     r0);
            atomicAdd(&rowbuf[rbase + mi * 16 + g + 8], r1);
        }
    }
    if (!diag) {
        #pragma unroll
        for (int ni = 0; ni < 4; ni++) {
            #pragma unroll
            for (int p = 0; p < 2; p++) {
                float v = colp[ni][p];
                v += __shfl_xor_sync(~0u, v, 4);
                v += __shfl_xor_sync(~0u, v, 8);
                v += __shfl_xor_sync(~0u, v, 16);
                if (lane < 4) atomicAdd(&colbuf[cbase + ni * 8 + lane * 2 + p], v);
            }
        }
    }
    __syncthreads();
    if (tid < BM) {
        atomicAdd(&g_rowsumE[I * BM + tid], rowbuf[tid]);
        if (!diag) atomicAdd(&g_rowsumE[J * BN + tid], colbuf[tid]);
    }
}

// fused: blocks [0,256) reduce split-k partials; blocks [256,272) row terms
__global__ void k_tail(const float* __restrict__ soft, const void* pwp) {
    if (blockIdx.x < 256) {
        int idx = blockIdx.x * 256 + threadIdx.x;
        float su = 0.f, sm = 0.f;
        {
            int d = idx >> 6, n = idx & 63;
            int mt = d >> 7, dl = d & 127;
            float s = 0.f;
            #pragma unroll
            for (int sp = 0; sp < KSPLIT; sp++)
                s += g_part[((size_t)(sp * 8 + mt) * 128 + dl) * NSM + n];
            if (n < C_SZ) su = s * s; else sm = s * s;
        }
        #pragma unroll
        for (int o = 16; o; o >>= 1) { su += __shfl_xor_sync(~0u, su, o); sm += __shfl_xor_sync(~0u, sm, o); }
        __shared__ float rs[8], rm[8];
        if ((threadIdx.x & 31) == 0) { rs[threadIdx.x >> 5] = su; rm[threadIdx.x >> 5] = sm; }
        __syncthreads();
        if (threadIdx.x < 8) {
            float a = rs[threadIdx.x], b = rm[threadIdx.x];
            #pragma unroll
            for (int o = 4; o; o >>= 1) { a += __shfl_xor_sync(0xff, a, o); b += __shfl_xor_sync(0xff, b, o); }
            if (threadIdx.x == 0) { atomicAdd(&g_sumU2, a); atomicAdd(&g_sumM2, b); }
        }
    } else {
        float pw = decode_pw(pwp);
        int i = (blockIdx.x - 256) * 256 + threadIdx.x;
        float term = 0.f;
        {
            int lbl = g_labels[i];
            float wsum = (float)(g_hist[lbl] - 1);
            const float* s = soft + (size_t)i * C_SZ;
            float d = 0.f;
            #pragma unroll
            for (int c = 0; c < C_SZ; c++) d += s[c] * g_Ssum[c];
            wsum += pw * d;
            term = wsum * logf(g_rowsumE[i]);
        }
        #pragma unroll
        for (int o = 16; o; o >>= 1) term += __shfl_xor_sync(~0u, term, o);
        __shared__ float red[8];
        if ((threadIdx.x & 31) == 0) red[threadIdx.x >> 5] = term;
        __syncthreads();
        if (threadIdx.x < 8) {
            float v = red[threadIdx.x];
            #pragma unroll
            for (int o = 4; o; o >>= 1) v += __shfl_xor_sync(0xff, v, o);
            if (threadIdx.x == 0) atomicAdd(&g_accLog, v);
        }
    }
}

__global__ void k_out(float* out, const void* pwp) {
    float pw = decode_pw(pwp);
    float P  = (g_sumM2 * S2INV - g_diagsum) * 10.0f;
    float SZ = (g_sumU2 * S2INV) * 10.0f;
    out[0] = (g_accLog - P - pw * SZ) / (float)B_SZ;
}

// ---------------- launch ----------------
extern "C" void kernel_launch(void* const* d_in, const int* in_sizes, int n_in,
                              void* d_out, int out_size) {
    const float* reps = (const float*)d_in[0];
    const float* soft = (const float*)d_in[1];
    const int*   lblp = (const int*)d_in[2];
    const void*  pwp  = d_in[3];
    float* out = (float*)d_out;
    (void)in_sizes; (void)n_in; (void)out_size;

    k_init<<<16, 256>>>(lblp);
    k_norm<<<B_SZ, 256>>>(reps, soft);
    k_small<<<dim3(8, KSPLIT), 256>>>(soft);
    k_gemm_q<<<NPAIR, 256>>>();
    k_tail<<<272, 256>>>(soft, pwp);
    k_out<<<1, 1>>>(out, pwp);
}